// round 1
// baseline (speedup 1.0000x reference)
#include <cuda_runtime.h>
#include <cuda_bf16.h>
#include <cstdint>

// ----------------------------------------------------------------------------
// CrossAttention: out = softmax((q_in Wq)(kv_in Wk)^T * scale) (kv_in Wv) Wo + bo
// b=4, p=8, n=512, dim=512, heads=8, dim_head=64
// Strategy: split-bf16 (hi/lo) 3-MMA GEMMs for fp32-grade accuracy on tensor
// pipe; full S materialization + row softmax (flash fusion deferred).
// ----------------------------------------------------------------------------

namespace {
constexpr int BM = 128, BN = 64, BK = 32, SPAD = 36;   // smem row stride (pad for bank conflicts)
constexpr int GEMM_THREADS = 256;
constexpr float ATTN_SCALE = 0.125f;                   // 64^-0.5
}

// Scratch (module-static device memory; allocation inside kernel_launch is forbidden)
__device__ float g_Q[16384 * 512];
__device__ float g_K[16384 * 512];
__device__ float g_V[16384 * 512];
__device__ float g_O[16384 * 512];
__device__ float g_S[67108864];   // 256 heads * 512 * 512

__device__ __forceinline__ void mma16816(float* d, const unsigned* a, const unsigned* b) {
    asm volatile(
        "mma.sync.aligned.m16n8k16.row.col.f32.bf16.bf16.f32 "
        "{%0,%1,%2,%3},{%4,%5,%6,%7},{%8,%9},{%0,%1,%2,%3};\n"
        : "+f"(d[0]), "+f"(d[1]), "+f"(d[2]), "+f"(d[3])
        : "r"(a[0]), "r"(a[1]), "r"(a[2]), "r"(a[3]), "r"(b[0]), "r"(b[1]));
}

__device__ __forceinline__ void split_bf16(float x, __nv_bfloat16& h, __nv_bfloat16& l) {
    h = __float2bfloat16(x);
    l = __float2bfloat16(x - __bfloat162float(h));
}

// Generic batched GEMM: C = alpha * A @ B (+bias), fp32 in/out, split-bf16 MMA inside.
// A: [M x K] row-major (lda). B: if TRANSB, [N x K] row-major (ldb); else [K x N] (ldb).
// Per-batch offsets: z = blockIdx.z decomposed as zo = z>>3 (b*p), zi = z&7 (head).
template <bool TRANSB>
__global__ __launch_bounds__(GEMM_THREADS)
void gemm_split_kernel(const float* __restrict__ A, const float* __restrict__ Bm,
                       float* __restrict__ C, const float* __restrict__ bias,
                       int M, int Nn, int K, int lda, int ldb, int ldc,
                       long long sA0, long long sA1, long long sB0, long long sB1,
                       long long sC0, long long sC1, float alpha)
{
    __shared__ __nv_bfloat16 sAh[BM][SPAD], sAl[BM][SPAD];
    __shared__ __nv_bfloat16 sBh[BN][SPAD], sBl[BN][SPAD];

    const int z = blockIdx.z;
    const long long zo = z >> 3, zi = z & 7;
    A  += zo * sA0 + zi * sA1;
    Bm += zo * sB0 + zi * sB1;
    C  += zo * sC0 + zi * sC1;

    const int tid  = threadIdx.x;
    const int lane = tid & 31, warp = tid >> 5;
    const int wm = warp >> 1, wn = warp & 1;       // 4x2 warp grid, 32x32 tiles
    const int g  = lane >> 2, tg = lane & 3;
    const int blockM = blockIdx.y * BM, blockN = blockIdx.x * BN;

    float acc[2][4][4];
    #pragma unroll
    for (int mt = 0; mt < 2; mt++)
        #pragma unroll
        for (int nt = 0; nt < 4; nt++)
            #pragma unroll
            for (int i = 0; i < 4; i++) acc[mt][nt][i] = 0.f;

    const int ktiles = K / BK;
    for (int kt = 0; kt < ktiles; kt++) {
        // ---- load A tile 128x32 (float4), split hi/lo ----
        #pragma unroll
        for (int i = tid; i < BM * BK / 4; i += GEMM_THREADS) {
            const int row = i >> 3;
            const int kq  = (i & 7) * 4;
            const float4 v = *(const float4*)(A + (size_t)(blockM + row) * lda + kt * BK + kq);
            const float vv[4] = {v.x, v.y, v.z, v.w};
            #pragma unroll
            for (int j = 0; j < 4; j++) {
                __nv_bfloat16 h, l;
                split_bf16(vv[j], h, l);
                sAh[row][kq + j] = h;
                sAl[row][kq + j] = l;
            }
        }
        // ---- load B tile, store as Bt[n][k] ----
        if (TRANSB) {
            #pragma unroll
            for (int i = tid; i < BN * BK / 4; i += GEMM_THREADS) {
                const int n  = i >> 3;
                const int kq = (i & 7) * 4;
                const float4 v = *(const float4*)(Bm + (size_t)(blockN + n) * ldb + kt * BK + kq);
                const float vv[4] = {v.x, v.y, v.z, v.w};
                #pragma unroll
                for (int j = 0; j < 4; j++) {
                    __nv_bfloat16 h, l;
                    split_bf16(vv[j], h, l);
                    sBh[n][kq + j] = h;
                    sBl[n][kq + j] = l;
                }
            }
        } else {
            #pragma unroll
            for (int i = tid; i < BK * BN; i += GEMM_THREADS) {
                const int k = i >> 6;       // / BN
                const int n = i & 63;       // % BN (coalesced along n)
                const float v = Bm[(size_t)(kt * BK + k) * ldb + blockN + n];
                __nv_bfloat16 h, l;
                split_bf16(v, h, l);
                sBh[n][k] = h;
                sBl[n][k] = l;
            }
        }
        __syncthreads();

        #pragma unroll
        for (int kk = 0; kk < BK; kk += 16) {
            unsigned ah[2][4], al[2][4], bh[4][2], bl[4][2];
            #pragma unroll
            for (int mt = 0; mt < 2; mt++) {
                const int r = wm * 32 + mt * 16 + g;
                const int c = kk + tg * 2;
                ah[mt][0] = *(const unsigned*)&sAh[r][c];
                ah[mt][1] = *(const unsigned*)&sAh[r + 8][c];
                ah[mt][2] = *(const unsigned*)&sAh[r][c + 8];
                ah[mt][3] = *(const unsigned*)&sAh[r + 8][c + 8];
                al[mt][0] = *(const unsigned*)&sAl[r][c];
                al[mt][1] = *(const unsigned*)&sAl[r + 8][c];
                al[mt][2] = *(const unsigned*)&sAl[r][c + 8];
                al[mt][3] = *(const unsigned*)&sAl[r + 8][c + 8];
            }
            #pragma unroll
            for (int nt = 0; nt < 4; nt++) {
                const int n = wn * 32 + nt * 8 + g;
                const int c = kk + tg * 2;
                bh[nt][0] = *(const unsigned*)&sBh[n][c];
                bh[nt][1] = *(const unsigned*)&sBh[n][c + 8];
                bl[nt][0] = *(const unsigned*)&sBl[n][c];
                bl[nt][1] = *(const unsigned*)&sBl[n][c + 8];
            }
            #pragma unroll
            for (int mt = 0; mt < 2; mt++)
                #pragma unroll
                for (int nt = 0; nt < 4; nt++) {
                    mma16816(acc[mt][nt], ah[mt], bh[nt]);   // hi*hi
                    mma16816(acc[mt][nt], ah[mt], bl[nt]);   // hi*lo
                    mma16816(acc[mt][nt], al[mt], bh[nt]);   // lo*hi
                }
        }
        __syncthreads();
    }

    // ---- epilogue ----
    #pragma unroll
    for (int mt = 0; mt < 2; mt++)
        #pragma unroll
        for (int nt = 0; nt < 4; nt++) {
            const int r  = blockM + wm * 32 + mt * 16 + g;
            const int cc = blockN + wn * 32 + nt * 8 + tg * 2;
            float b0 = 0.f, b1 = 0.f;
            if (bias) { b0 = bias[cc]; b1 = bias[cc + 1]; }
            C[(size_t)r * ldc + cc]           = alpha * acc[mt][nt][0] + b0;
            C[(size_t)r * ldc + cc + 1]       = alpha * acc[mt][nt][1] + b1;
            C[(size_t)(r + 8) * ldc + cc]     = alpha * acc[mt][nt][2] + b0;
            C[(size_t)(r + 8) * ldc + cc + 1] = alpha * acc[mt][nt][3] + b1;
        }
}

// Row softmax over rows of length 512, one warp per row.
__global__ __launch_bounds__(256)
void softmax_rows_kernel(float* __restrict__ S, int rows)
{
    const int warp = (blockIdx.x * blockDim.x + threadIdx.x) >> 5;
    const int lane = threadIdx.x & 31;
    if (warp >= rows) return;
    float* row = S + (size_t)warp * 512;

    float v[16];
    float m = -1e30f;
    #pragma unroll
    for (int i = 0; i < 16; i++) {
        v[i] = row[lane + i * 32];
        m = fmaxf(m, v[i]);
    }
    #pragma unroll
    for (int off = 16; off > 0; off >>= 1)
        m = fmaxf(m, __shfl_xor_sync(0xffffffffu, m, off));

    float s = 0.f;
    #pragma unroll
    for (int i = 0; i < 16; i++) {
        v[i] = __expf(v[i] - m);
        s += v[i];
    }
    #pragma unroll
    for (int off = 16; off > 0; off >>= 1)
        s += __shfl_xor_sync(0xffffffffu, s, off);

    const float inv = 1.f / s;
    #pragma unroll
    for (int i = 0; i < 16; i++)
        row[lane + i * 32] = v[i] * inv;
}

extern "C" void kernel_launch(void* const* d_in, const int* in_sizes, int n_in,
                              void* d_out, int out_size)
{
    const float* q_in  = (const float*)d_in[0];
    const float* kv_in = (const float*)d_in[1];
    const float* Wq    = (const float*)d_in[2];
    const float* Wk    = (const float*)d_in[3];
    const float* Wv    = (const float*)d_in[4];
    const float* Wo    = (const float*)d_in[5];
    const float* bo    = (const float*)d_in[6];
    float* out = (float*)d_out;

    float *Q, *K, *V, *O, *S;
    cudaGetSymbolAddress((void**)&Q, g_Q);
    cudaGetSymbolAddress((void**)&K, g_K);
    cudaGetSymbolAddress((void**)&V, g_V);
    cudaGetSymbolAddress((void**)&O, g_O);
    cudaGetSymbolAddress((void**)&S, g_S);

    const int M = 16384, D = 512;

    // 1-3: Q/K/V projections: [16384,512] @ [512,512]
    {
        dim3 grid(D / BN, M / BM, 1);
        gemm_split_kernel<false><<<grid, GEMM_THREADS>>>(
            q_in, Wq, Q, nullptr, M, D, D, D, D, D, 0, 0, 0, 0, 0, 0, 1.f);
        gemm_split_kernel<false><<<grid, GEMM_THREADS>>>(
            kv_in, Wk, K, nullptr, M, D, D, D, D, D, 0, 0, 0, 0, 0, 0, 1.f);
        gemm_split_kernel<false><<<grid, GEMM_THREADS>>>(
            kv_in, Wv, V, nullptr, M, D, D, D, D, D, 0, 0, 0, 0, 0, 0, 1.f);
    }

    // 4: S = Q @ K^T * scale, batched over 256 (b*p, h) pairs. M=N=512, K=64.
    {
        dim3 grid(512 / BN, 512 / BM, 256);
        gemm_split_kernel<true><<<grid, GEMM_THREADS>>>(
            Q, K, S, nullptr, 512, 512, 64, 512, 512, 512,
            /*sA*/ 262144LL, 64LL, /*sB*/ 262144LL, 64LL,
            /*sC*/ 2097152LL, 262144LL, ATTN_SCALE);
    }

    // 5: softmax over 256*512 rows of length 512
    softmax_rows_kernel<<<(256 * 512) / 8, 256>>>(S, 256 * 512);

    // 6: O = P @ V, batched. M=512, N=64, K=512.
    {
        dim3 grid(64 / BN, 512 / BM, 256);
        gemm_split_kernel<false><<<grid, GEMM_THREADS>>>(
            S, V, O, nullptr, 512, 64, 512, 512, 512, 512,
            /*sA*/ 2097152LL, 262144LL, /*sB*/ 262144LL, 64LL,
            /*sC*/ 262144LL, 64LL, 1.f);
    }

    // 7: out = O @ Wo + bo
    {
        dim3 grid(D / BN, M / BM, 1);
        gemm_split_kernel<false><<<grid, GEMM_THREADS>>>(
            O, Wo, out, bo, M, D, D, D, D, D, 0, 0, 0, 0, 0, 0, 1.f);
    }
}

// round 2
// speedup vs baseline: 1.1758x; 1.1758x over previous
#include <cuda_runtime.h>
#include <cuda_bf16.h>
#include <cstdint>

// ----------------------------------------------------------------------------
// CrossAttention, fused flash version.
// b=4, p=8, n=512, dim=512, heads=8, dim_head=64; scale=0.125 (exact pow2,
// folded into Q projection).
// Pipeline:
//   split(q_in,kv_in,W*)  ->  3 proj GEMMs (split-bf16 out; Q pre-scaled)
//   -> flash attention (S,P in registers, online softmax, split-bf16 O out)
//   -> out GEMM (+bias, fp32 out)
// All matmuls use the 3-MMA split-bf16 trick (Ah*Bh + Ah*Bl + Al*Bh) for
// fp32-grade accuracy on the tensor pipe.
// ----------------------------------------------------------------------------

namespace {
constexpr int NTOK = 16384;          // 4*8*512 tokens
constexpr int DMODEL = 512;
constexpr int NELEM = NTOK * DMODEL; // 8388608
constexpr int WELEM = DMODEL * DMODEL;
}

// ---- scratch (static device memory; runtime allocation is forbidden) ----
__device__ __nv_bfloat16 g_qh[NELEM],  g_ql[NELEM];
__device__ __nv_bfloat16 g_kvh[NELEM], g_kvl[NELEM];
__device__ __nv_bfloat16 g_wh[4 * WELEM], g_wl[4 * WELEM];  // Wq,Wk,Wv,Wo
__device__ __nv_bfloat16 g_Qh[NELEM], g_Ql[NELEM];
__device__ __nv_bfloat16 g_Kh[NELEM], g_Kl[NELEM];
__device__ __nv_bfloat16 g_Vh[NELEM], g_Vl[NELEM];
__device__ __nv_bfloat16 g_Oh[NELEM], g_Ol[NELEM];

__device__ __forceinline__ void mma16816(float* d, const unsigned* a, const unsigned* b) {
    asm volatile(
        "mma.sync.aligned.m16n8k16.row.col.f32.bf16.bf16.f32 "
        "{%0,%1,%2,%3},{%4,%5,%6,%7},{%8,%9},{%0,%1,%2,%3};\n"
        : "+f"(d[0]), "+f"(d[1]), "+f"(d[2]), "+f"(d[3])
        : "r"(a[0]), "r"(a[1]), "r"(a[2]), "r"(a[3]), "r"(b[0]), "r"(b[1]));
}

__device__ __forceinline__ unsigned pack2(__nv_bfloat16 x, __nv_bfloat16 y) {
    __nv_bfloat162 t{x, y};
    return *reinterpret_cast<unsigned*>(&t);
}

__device__ __forceinline__ void split_pack2(float x, float y, unsigned& hp, unsigned& lp) {
    __nv_bfloat16 hx = __float2bfloat16(x), hy = __float2bfloat16(y);
    __nv_bfloat16 lx = __float2bfloat16(x - __bfloat162float(hx));
    __nv_bfloat16 ly = __float2bfloat16(y - __bfloat162float(hy));
    hp = pack2(hx, hy);
    lp = pack2(lx, ly);
}

// ---- fp32 -> (hi, lo) bf16 split, vectorized ----
__global__ __launch_bounds__(256)
void split_kernel(const float* __restrict__ src, __nv_bfloat16* __restrict__ dh,
                  __nv_bfloat16* __restrict__ dl, int n4)
{
    int i = blockIdx.x * blockDim.x + threadIdx.x;
    if (i >= n4) return;
    float4 v = reinterpret_cast<const float4*>(src)[i];
    unsigned h01, l01, h23, l23;
    split_pack2(v.x, v.y, h01, l01);
    split_pack2(v.z, v.w, h23, l23);
    uint2 hv{h01, h23}, lv{l01, l23};
    reinterpret_cast<uint2*>(dh)[i] = hv;
    reinterpret_cast<uint2*>(dl)[i] = lv;
}

// ----------------------------------------------------------------------------
// Dense GEMM: C = alpha * A @ B (+bias). A [16384 x 512], B [512 x 512],
// pre-split bf16 inputs. OUT_SPLIT=1: write (Ch, Cl) bf16; else fp32 + bias.
// ----------------------------------------------------------------------------
template <int OUT_SPLIT>
__global__ __launch_bounds__(256)
void gemm_bf16_kernel(const __nv_bfloat16* __restrict__ Ah, const __nv_bfloat16* __restrict__ Al,
                      const __nv_bfloat16* __restrict__ Bh, const __nv_bfloat16* __restrict__ Bl,
                      float* __restrict__ Cf,
                      __nv_bfloat16* __restrict__ Ch, __nv_bfloat16* __restrict__ Cl,
                      const float* __restrict__ bias, float alpha)
{
    __shared__ __nv_bfloat16 sAh[128][40], sAl[128][40];
    __shared__ __nv_bfloat16 sBh[64][40],  sBl[64][40];

    const int tid  = threadIdx.x;
    const int lane = tid & 31, warp = tid >> 5;
    const int wm = warp >> 1, wn = warp & 1;
    const int g  = lane >> 2, tg = lane & 3;
    const int blockM = blockIdx.y * 128, blockN = blockIdx.x * 64;

    float acc[2][4][4];
    #pragma unroll
    for (int mt = 0; mt < 2; mt++)
        #pragma unroll
        for (int nt = 0; nt < 4; nt++)
            #pragma unroll
            for (int i = 0; i < 4; i++) acc[mt][nt][i] = 0.f;

    for (int kt = 0; kt < 16; kt++) {
        // A tile 128x32: 512 uint4 per array
        #pragma unroll
        for (int j = 0; j < 2; j++) {
            const int idx = tid + j * 256;
            const int row = idx >> 2, q = (idx & 3) * 8;
            const size_t go = (size_t)(blockM + row) * 512 + kt * 32 + q;
            *(uint4*)&sAh[row][q] = *(const uint4*)(Ah + go);
            *(uint4*)&sAl[row][q] = *(const uint4*)(Al + go);
        }
        // B tile 32x64 -> sB[n][k]
        #pragma unroll
        for (int j = 0; j < 4; j++) {
            const int idx = tid + j * 256;
            const int k = idx >> 5, n2 = (idx & 31) * 2;
            const size_t go = (size_t)(kt * 32 + k) * 512 + blockN + n2;
            __nv_bfloat162 ph = *(const __nv_bfloat162*)(Bh + go);
            __nv_bfloat162 pl = *(const __nv_bfloat162*)(Bl + go);
            sBh[n2][k] = ph.x; sBh[n2 + 1][k] = ph.y;
            sBl[n2][k] = pl.x; sBl[n2 + 1][k] = pl.y;
        }
        __syncthreads();

        #pragma unroll
        for (int kk = 0; kk < 32; kk += 16) {
            unsigned ah[2][4], al[2][4], bh[4][2], bl[4][2];
            #pragma unroll
            for (int mt = 0; mt < 2; mt++) {
                const int r = wm * 32 + mt * 16 + g;
                const int c = kk + tg * 2;
                ah[mt][0] = *(const unsigned*)&sAh[r][c];
                ah[mt][1] = *(const unsigned*)&sAh[r + 8][c];
                ah[mt][2] = *(const unsigned*)&sAh[r][c + 8];
                ah[mt][3] = *(const unsigned*)&sAh[r + 8][c + 8];
                al[mt][0] = *(const unsigned*)&sAl[r][c];
                al[mt][1] = *(const unsigned*)&sAl[r + 8][c];
                al[mt][2] = *(const unsigned*)&sAl[r][c + 8];
                al[mt][3] = *(const unsigned*)&sAl[r + 8][c + 8];
            }
            #pragma unroll
            for (int nt = 0; nt < 4; nt++) {
                const int n = wn * 32 + nt * 8 + g;
                const int c = kk + tg * 2;
                bh[nt][0] = *(const unsigned*)&sBh[n][c];
                bh[nt][1] = *(const unsigned*)&sBh[n][c + 8];
                bl[nt][0] = *(const unsigned*)&sBl[n][c];
                bl[nt][1] = *(const unsigned*)&sBl[n][c + 8];
            }
            #pragma unroll
            for (int mt = 0; mt < 2; mt++)
                #pragma unroll
                for (int nt = 0; nt < 4; nt++) {
                    mma16816(acc[mt][nt], ah[mt], bh[nt]);
                    mma16816(acc[mt][nt], ah[mt], bl[nt]);
                    mma16816(acc[mt][nt], al[mt], bh[nt]);
                }
        }
        __syncthreads();
    }

    #pragma unroll
    for (int mt = 0; mt < 2; mt++)
        #pragma unroll
        for (int nt = 0; nt < 4; nt++) {
            const int r  = blockM + wm * 32 + mt * 16 + g;
            const int cc = blockN + wn * 32 + nt * 8 + tg * 2;
            const float v0 = alpha * acc[mt][nt][0];
            const float v1 = alpha * acc[mt][nt][1];
            const float v2 = alpha * acc[mt][nt][2];
            const float v3 = alpha * acc[mt][nt][3];
            if (OUT_SPLIT) {
                unsigned hp, lp;
                split_pack2(v0, v1, hp, lp);
                *(unsigned*)&Ch[(size_t)r * 512 + cc] = hp;
                *(unsigned*)&Cl[(size_t)r * 512 + cc] = lp;
                split_pack2(v2, v3, hp, lp);
                *(unsigned*)&Ch[(size_t)(r + 8) * 512 + cc] = hp;
                *(unsigned*)&Cl[(size_t)(r + 8) * 512 + cc] = lp;
            } else {
                const float b0 = bias[cc], b1 = bias[cc + 1];
                Cf[(size_t)r * 512 + cc]           = v0 + b0;
                Cf[(size_t)r * 512 + cc + 1]       = v1 + b1;
                Cf[(size_t)(r + 8) * 512 + cc]     = v2 + b0;
                Cf[(size_t)(r + 8) * 512 + cc + 1] = v3 + b1;
            }
        }
}

// ----------------------------------------------------------------------------
// Flash attention: per block = one (b*p, head) z and one 128-query tile.
// Q (pre-scaled) kept in registers; K/V tiles (64 keys) staged in smem;
// S and P live in registers; online softmax; split-bf16 O written out.
// ----------------------------------------------------------------------------
__global__ __launch_bounds__(256)
void flash_kernel(const __nv_bfloat16* __restrict__ Qh, const __nv_bfloat16* __restrict__ Ql,
                  const __nv_bfloat16* __restrict__ Kh, const __nv_bfloat16* __restrict__ Kl,
                  const __nv_bfloat16* __restrict__ Vh, const __nv_bfloat16* __restrict__ Vl,
                  __nv_bfloat16* __restrict__ Oh, __nv_bfloat16* __restrict__ Ol)
{
    __shared__ __nv_bfloat16 sKh[64][72], sKl[64][72];
    __shared__ __nv_bfloat16 sVth[64][72], sVtl[64][72];   // transposed: [dim][key]

    const int z = blockIdx.y;
    const long long zo = z >> 3, zi = z & 7;
    const size_t base = (size_t)zo * 512 * 512 + (size_t)zi * 64;  // + row*512 + col

    const int tid  = threadIdx.x;
    const int lane = tid & 31, warp = tid >> 5;
    const int g = lane >> 2, tg = lane & 3;
    const int rowA = blockIdx.x * 128 + warp * 16 + g;   // this thread's row (and +8)

    // ---- Q fragments (resident) ----
    unsigned qh[4][4], ql[4][4];
    #pragma unroll
    for (int kc = 0; kc < 4; kc++) {
        const int c = kc * 16 + tg * 2;
        qh[kc][0] = *(const unsigned*)&Qh[base + (size_t)rowA * 512 + c];
        qh[kc][1] = *(const unsigned*)&Qh[base + (size_t)(rowA + 8) * 512 + c];
        qh[kc][2] = *(const unsigned*)&Qh[base + (size_t)rowA * 512 + c + 8];
        qh[kc][3] = *(const unsigned*)&Qh[base + (size_t)(rowA + 8) * 512 + c + 8];
        ql[kc][0] = *(const unsigned*)&Ql[base + (size_t)rowA * 512 + c];
        ql[kc][1] = *(const unsigned*)&Ql[base + (size_t)(rowA + 8) * 512 + c];
        ql[kc][2] = *(const unsigned*)&Ql[base + (size_t)rowA * 512 + c + 8];
        ql[kc][3] = *(const unsigned*)&Ql[base + (size_t)(rowA + 8) * 512 + c + 8];
    }

    float o[8][4];
    #pragma unroll
    for (int nd = 0; nd < 8; nd++)
        #pragma unroll
        for (int i = 0; i < 4; i++) o[nd][i] = 0.f;
    float m0 = -1e30f, m1 = -1e30f, l0 = 0.f, l1 = 0.f;

    for (int kt = 0; kt < 8; kt++) {
        // ---- stage K tile [64 keys x 64 dims] ----
        #pragma unroll
        for (int j = 0; j < 2; j++) {
            const int idx = tid + j * 256;
            const int row = idx >> 3, q = (idx & 7) * 8;
            const size_t go = base + (size_t)(kt * 64 + row) * 512 + q;
            *(uint4*)&sKh[row][q] = *(const uint4*)(Kh + go);
            *(uint4*)&sKl[row][q] = *(const uint4*)(Kl + go);
        }
        // ---- stage V tile transposed [dim][key] ----
        #pragma unroll
        for (int j = 0; j < 2; j++) {
            const int idx = tid + j * 256;
            const int key = idx >> 3, dq = (idx & 7) * 8;
            const size_t go = base + (size_t)(kt * 64 + key) * 512 + dq;
            const uint4 vh = *(const uint4*)(Vh + go);
            const uint4 vl = *(const uint4*)(Vl + go);
            const unsigned uh[4] = {vh.x, vh.y, vh.z, vh.w};
            const unsigned ul[4] = {vl.x, vl.y, vl.z, vl.w};
            #pragma unroll
            for (int p = 0; p < 4; p++) {
                __nv_bfloat162 ph = *(const __nv_bfloat162*)&uh[p];
                __nv_bfloat162 pl = *(const __nv_bfloat162*)&ul[p];
                sVth[dq + p * 2][key]     = ph.x;
                sVth[dq + p * 2 + 1][key] = ph.y;
                sVtl[dq + p * 2][key]     = pl.x;
                sVtl[dq + p * 2 + 1][key] = pl.y;
            }
        }
        __syncthreads();

        // ---- S = Qs @ K^T (scaled already) ----
        float s[8][4];
        #pragma unroll
        for (int nt = 0; nt < 8; nt++)
            #pragma unroll
            for (int i = 0; i < 4; i++) s[nt][i] = 0.f;

        #pragma unroll
        for (int kc = 0; kc < 4; kc++) {
            #pragma unroll
            for (int nt = 0; nt < 8; nt++) {
                const int n = nt * 8 + g;
                const int c = kc * 16 + tg * 2;
                unsigned bh[2], bl[2];
                bh[0] = *(const unsigned*)&sKh[n][c];
                bh[1] = *(const unsigned*)&sKh[n][c + 8];
                bl[0] = *(const unsigned*)&sKl[n][c];
                bl[1] = *(const unsigned*)&sKl[n][c + 8];
                mma16816(s[nt], qh[kc], bh);
                mma16816(s[nt], qh[kc], bl);
                mma16816(s[nt], ql[kc], bh);
            }
        }

        // ---- online softmax ----
        float r0 = -1e30f, r1 = -1e30f;
        #pragma unroll
        for (int nt = 0; nt < 8; nt++) {
            r0 = fmaxf(r0, fmaxf(s[nt][0], s[nt][1]));
            r1 = fmaxf(r1, fmaxf(s[nt][2], s[nt][3]));
        }
        r0 = fmaxf(r0, __shfl_xor_sync(0xffffffffu, r0, 1));
        r0 = fmaxf(r0, __shfl_xor_sync(0xffffffffu, r0, 2));
        r1 = fmaxf(r1, __shfl_xor_sync(0xffffffffu, r1, 1));
        r1 = fmaxf(r1, __shfl_xor_sync(0xffffffffu, r1, 2));
        const float m0n = fmaxf(m0, r0), m1n = fmaxf(m1, r1);
        const float a0 = __expf(m0 - m0n), a1 = __expf(m1 - m1n);

        float ps0 = 0.f, ps1 = 0.f;
        #pragma unroll
        for (int nt = 0; nt < 8; nt++) {
            s[nt][0] = __expf(s[nt][0] - m0n);
            s[nt][1] = __expf(s[nt][1] - m0n);
            s[nt][2] = __expf(s[nt][2] - m1n);
            s[nt][3] = __expf(s[nt][3] - m1n);
            ps0 += s[nt][0] + s[nt][1];
            ps1 += s[nt][2] + s[nt][3];
        }
        m0 = m0n; m1 = m1n;
        l0 = l0 * a0 + ps0;      // per-thread partial; quad-reduced at the end
        l1 = l1 * a1 + ps1;
        #pragma unroll
        for (int nd = 0; nd < 8; nd++) {
            o[nd][0] *= a0; o[nd][1] *= a0;
            o[nd][2] *= a1; o[nd][3] *= a1;
        }

        // ---- O += P @ V ----
        #pragma unroll
        for (int kc = 0; kc < 4; kc++) {
            unsigned pah[4], pal[4];
            split_pack2(s[2 * kc][0],     s[2 * kc][1],     pah[0], pal[0]);
            split_pack2(s[2 * kc][2],     s[2 * kc][3],     pah[1], pal[1]);
            split_pack2(s[2 * kc + 1][0], s[2 * kc + 1][1], pah[2], pal[2]);
            split_pack2(s[2 * kc + 1][2], s[2 * kc + 1][3], pah[3], pal[3]);
            #pragma unroll
            for (int nd = 0; nd < 8; nd++) {
                const int d = nd * 8 + g;
                const int c = kc * 16 + tg * 2;
                unsigned vbh[2], vbl[2];
                vbh[0] = *(const unsigned*)&sVth[d][c];
                vbh[1] = *(const unsigned*)&sVth[d][c + 8];
                vbl[0] = *(const unsigned*)&sVtl[d][c];
                vbl[1] = *(const unsigned*)&sVtl[d][c + 8];
                mma16816(o[nd], pah, vbh);
                mma16816(o[nd], pah, vbl);
                mma16816(o[nd], pal, vbh);
            }
        }
        __syncthreads();
    }

    // ---- finalize: reduce l over quad, divide, split-write O ----
    l0 += __shfl_xor_sync(0xffffffffu, l0, 1);
    l0 += __shfl_xor_sync(0xffffffffu, l0, 2);
    l1 += __shfl_xor_sync(0xffffffffu, l1, 1);
    l1 += __shfl_xor_sync(0xffffffffu, l1, 2);
    const float inv0 = 1.f / l0, inv1 = 1.f / l1;

    #pragma unroll
    for (int nd = 0; nd < 8; nd++) {
        const int cc = nd * 8 + tg * 2;
        unsigned hp, lp;
        split_pack2(o[nd][0] * inv0, o[nd][1] * inv0, hp, lp);
        *(unsigned*)&Oh[base + (size_t)rowA * 512 + cc] = hp;
        *(unsigned*)&Ol[base + (size_t)rowA * 512 + cc] = lp;
        split_pack2(o[nd][2] * inv1, o[nd][3] * inv1, hp, lp);
        *(unsigned*)&Oh[base + (size_t)(rowA + 8) * 512 + cc] = hp;
        *(unsigned*)&Ol[base + (size_t)(rowA + 8) * 512 + cc] = lp;
    }
}

extern "C" void kernel_launch(void* const* d_in, const int* in_sizes, int n_in,
                              void* d_out, int out_size)
{
    const float* q_in  = (const float*)d_in[0];
    const float* kv_in = (const float*)d_in[1];
    const float* Wq    = (const float*)d_in[2];
    const float* Wk    = (const float*)d_in[3];
    const float* Wv    = (const float*)d_in[4];
    const float* Wo    = (const float*)d_in[5];
    const float* bo    = (const float*)d_in[6];
    float* out = (float*)d_out;

    __nv_bfloat16 *qh, *ql, *kvh, *kvl, *wh, *wl;
    __nv_bfloat16 *Qh, *Ql, *Kh, *Kl, *Vh, *Vl, *Oh, *Ol;
    cudaGetSymbolAddress((void**)&qh,  g_qh);  cudaGetSymbolAddress((void**)&ql,  g_ql);
    cudaGetSymbolAddress((void**)&kvh, g_kvh); cudaGetSymbolAddress((void**)&kvl, g_kvl);
    cudaGetSymbolAddress((void**)&wh,  g_wh);  cudaGetSymbolAddress((void**)&wl,  g_wl);
    cudaGetSymbolAddress((void**)&Qh,  g_Qh);  cudaGetSymbolAddress((void**)&Ql,  g_Ql);
    cudaGetSymbolAddress((void**)&Kh,  g_Kh);  cudaGetSymbolAddress((void**)&Kl,  g_Kl);
    cudaGetSymbolAddress((void**)&Vh,  g_Vh);  cudaGetSymbolAddress((void**)&Vl,  g_Vl);
    cudaGetSymbolAddress((void**)&Oh,  g_Oh);  cudaGetSymbolAddress((void**)&Ol,  g_Ol);

    // 1) pre-split inputs and weights
    split_kernel<<<(NELEM / 4 + 255) / 256, 256>>>(q_in,  qh,  ql,  NELEM / 4);
    split_kernel<<<(NELEM / 4 + 255) / 256, 256>>>(kv_in, kvh, kvl, NELEM / 4);
    split_kernel<<<(WELEM / 4 + 255) / 256, 256>>>(Wq, wh,             wl,             WELEM / 4);
    split_kernel<<<(WELEM / 4 + 255) / 256, 256>>>(Wk, wh + WELEM,     wl + WELEM,     WELEM / 4);
    split_kernel<<<(WELEM / 4 + 255) / 256, 256>>>(Wv, wh + 2 * WELEM, wl + 2 * WELEM, WELEM / 4);
    split_kernel<<<(WELEM / 4 + 255) / 256, 256>>>(Wo, wh + 3 * WELEM, wl + 3 * WELEM, WELEM / 4);

    // 2) projections (split-bf16 outputs; Q pre-scaled by 0.125)
    dim3 ggrid(512 / 64, NTOK / 128, 1);
    gemm_bf16_kernel<1><<<ggrid, 256>>>(qh,  ql,  wh,             wl,             nullptr, Qh, Ql, nullptr, 0.125f);
    gemm_bf16_kernel<1><<<ggrid, 256>>>(kvh, kvl, wh + WELEM,     wl + WELEM,     nullptr, Kh, Kl, nullptr, 1.f);
    gemm_bf16_kernel<1><<<ggrid, 256>>>(kvh, kvl, wh + 2 * WELEM, wl + 2 * WELEM, nullptr, Vh, Vl, nullptr, 1.f);

    // 3) fused flash attention
    flash_kernel<<<dim3(4, 256), 256>>>(Qh, Ql, Kh, Kl, Vh, Vl, Oh, Ol);

    // 4) output projection + bias (fp32 out)
    gemm_bf16_kernel<0><<<ggrid, 256>>>(Oh, Ol, wh + 3 * WELEM, wl + 3 * WELEM, out, nullptr, nullptr, bo, 1.f);
}

// round 3
// speedup vs baseline: 1.9604x; 1.6673x over previous
#include <cuda_runtime.h>
#include <cuda_bf16.h>
#include <cstdint>

// ----------------------------------------------------------------------------
// CrossAttention: split-bf16 (3-MMA) everywhere; flash-fused attention.
// This round: 128x128 dense GEMM tiles, ldmatrix fragment loads, cp.async
// double-buffered pipeline; flash uses ldmatrix + trans-ldmatrix for V.
// ----------------------------------------------------------------------------

namespace {
constexpr int NTOK = 16384;
constexpr int DMODEL = 512;
constexpr int NELEM = NTOK * DMODEL;
constexpr int WELEM = DMODEL * DMODEL;

// dense smem layout (elements)
constexpr int APAD = 40;                 // 80B row stride: conflict-free ldsm
constexpr int BPAD = 136;                // 272B row stride: conflict-free ldsm
constexpr int ASZ = 128 * APAD;          // 5120
constexpr int BSZ = 32 * BPAD;           // 4352
constexpr int STG = 2 * ASZ + 2 * BSZ;   // 18944 elements per stage
constexpr int SMEM_DENSE = 2 * STG * 2;  // bytes = 75776
}

__device__ __nv_bfloat16 g_qh[NELEM],  g_ql[NELEM];
__device__ __nv_bfloat16 g_kvh[NELEM], g_kvl[NELEM];
__device__ __nv_bfloat16 g_wh[4 * WELEM], g_wl[4 * WELEM];
__device__ __nv_bfloat16 g_Qh[NELEM], g_Ql[NELEM];
__device__ __nv_bfloat16 g_Kh[NELEM], g_Kl[NELEM];
__device__ __nv_bfloat16 g_Vh[NELEM], g_Vl[NELEM];
__device__ __nv_bfloat16 g_Oh[NELEM], g_Ol[NELEM];

__device__ __forceinline__ void mma16816(float* d, const unsigned* a, const unsigned* b) {
    asm volatile(
        "mma.sync.aligned.m16n8k16.row.col.f32.bf16.bf16.f32 "
        "{%0,%1,%2,%3},{%4,%5,%6,%7},{%8,%9},{%0,%1,%2,%3};\n"
        : "+f"(d[0]), "+f"(d[1]), "+f"(d[2]), "+f"(d[3])
        : "r"(a[0]), "r"(a[1]), "r"(a[2]), "r"(a[3]), "r"(b[0]), "r"(b[1]));
}

__device__ __forceinline__ unsigned smem_u32(const void* p) {
    return (unsigned)__cvta_generic_to_shared(p);
}
__device__ __forceinline__ void ldsm_x4(unsigned* r, unsigned addr) {
    asm volatile("ldmatrix.sync.aligned.m8n8.x4.shared.b16 {%0,%1,%2,%3}, [%4];"
                 : "=r"(r[0]), "=r"(r[1]), "=r"(r[2]), "=r"(r[3]) : "r"(addr));
}
__device__ __forceinline__ void ldsm_x4_t(unsigned* r, unsigned addr) {
    asm volatile("ldmatrix.sync.aligned.m8n8.x4.trans.shared.b16 {%0,%1,%2,%3}, [%4];"
                 : "=r"(r[0]), "=r"(r[1]), "=r"(r[2]), "=r"(r[3]) : "r"(addr));
}
__device__ __forceinline__ void cp16(unsigned dst, const void* src) {
    asm volatile("cp.async.cg.shared.global [%0], [%1], 16;\n" :: "r"(dst), "l"(src));
}
__device__ __forceinline__ void cp_commit() { asm volatile("cp.async.commit_group;\n" ::: "memory"); }
__device__ __forceinline__ void cp_wait0()  { asm volatile("cp.async.wait_group 0;\n" ::: "memory"); }

__device__ __forceinline__ unsigned pack2(__nv_bfloat16 x, __nv_bfloat16 y) {
    __nv_bfloat162 t{x, y};
    return *reinterpret_cast<unsigned*>(&t);
}
__device__ __forceinline__ void split_pack2(float x, float y, unsigned& hp, unsigned& lp) {
    __nv_bfloat16 hx = __float2bfloat16(x), hy = __float2bfloat16(y);
    __nv_bfloat16 lx = __float2bfloat16(x - __bfloat162float(hx));
    __nv_bfloat16 ly = __float2bfloat16(y - __bfloat162float(hy));
    hp = pack2(hx, hy);
    lp = pack2(lx, ly);
}

__global__ __launch_bounds__(256)
void split_kernel(const float* __restrict__ src, __nv_bfloat16* __restrict__ dh,
                  __nv_bfloat16* __restrict__ dl, int n4)
{
    int i = blockIdx.x * blockDim.x + threadIdx.x;
    if (i >= n4) return;
    float4 v = reinterpret_cast<const float4*>(src)[i];
    unsigned h01, l01, h23, l23;
    split_pack2(v.x, v.y, h01, l01);
    split_pack2(v.z, v.w, h23, l23);
    uint2 hv{h01, h23}, lv{l01, l23};
    reinterpret_cast<uint2*>(dh)[i] = hv;
    reinterpret_cast<uint2*>(dl)[i] = lv;
}

// ----------------------------------------------------------------------------
// Dense GEMM: C = alpha * A @ B (+bias). A [16384 x 512] row-major split bf16,
// B [512 x 512] row-major split bf16 (loaded via trans-ldmatrix).
// CTA tile 128x128, BK=32, 8 warps (2x4), double-buffered cp.async.
// ----------------------------------------------------------------------------
template <int OUT_SPLIT>
__global__ __launch_bounds__(256)
void gemm_bf16_kernel(const __nv_bfloat16* __restrict__ Ah, const __nv_bfloat16* __restrict__ Al,
                      const __nv_bfloat16* __restrict__ Bh, const __nv_bfloat16* __restrict__ Bl,
                      float* __restrict__ Cf,
                      __nv_bfloat16* __restrict__ Ch, __nv_bfloat16* __restrict__ Cl,
                      const float* __restrict__ bias, float alpha)
{
    extern __shared__ __nv_bfloat16 sm[];

    const int tid  = threadIdx.x;
    const int lane = tid & 31, warp = tid >> 5;
    const int wm = warp >> 2, wn = warp & 3;          // 2x4 warp grid, 64x32 tiles
    const int g  = lane >> 2, tg = lane & 3;
    const int lrow = lane & 7, lsel = lane >> 3;
    const int blockM = blockIdx.y * 128, blockN = blockIdx.x * 128;

    // cp.async per-thread coordinates
    const int arow = tid >> 2, acol = (tid & 3) * 8;  // A: rows arow + j*64
    const int brow = tid >> 4, bcol = (tid & 15) * 8; // B: rows brow + j*16

    float acc[4][4][4];
    #pragma unroll
    for (int mt = 0; mt < 4; mt++)
        #pragma unroll
        for (int nt = 0; nt < 4; nt++)
            #pragma unroll
            for (int i = 0; i < 4; i++) acc[mt][nt][i] = 0.f;

    auto load_tile = [&](int kt, int s) {
        __nv_bfloat16* base = sm + s * STG;
        #pragma unroll
        for (int j = 0; j < 2; j++) {
            const int r = arow + j * 64;
            const size_t go = (size_t)(blockM + r) * 512 + kt * 32 + acol;
            cp16(smem_u32(base + r * APAD + acol),             Ah + go);
            cp16(smem_u32(base + ASZ + r * APAD + acol),       Al + go);
        }
        #pragma unroll
        for (int j = 0; j < 2; j++) {
            const int k = brow + j * 16;
            const size_t go = (size_t)(kt * 32 + k) * 512 + blockN + bcol;
            cp16(smem_u32(base + 2 * ASZ + k * BPAD + bcol),       Bh + go);
            cp16(smem_u32(base + 2 * ASZ + BSZ + k * BPAD + bcol), Bl + go);
        }
    };

    load_tile(0, 0);
    cp_commit();

    int buf = 0;
    for (int kt = 0; kt < 16; kt++) {
        cp_wait0();
        __syncthreads();
        if (kt < 15) { load_tile(kt + 1, buf ^ 1); cp_commit(); }

        const __nv_bfloat16* base = sm + buf * STG;
        #pragma unroll
        for (int kk = 0; kk < 32; kk += 16) {
            unsigned ah[4][4], al[4][4], bh[2][4], bl[2][4];
            #pragma unroll
            for (int mt = 0; mt < 4; mt++) {
                const int r0 = wm * 64 + mt * 16;
                const unsigned ea = smem_u32(base + (r0 + (lsel & 1) * 8 + lrow) * APAD
                                             + kk + (lsel >> 1) * 8);
                ldsm_x4(ah[mt], ea);
                ldsm_x4(al[mt], ea + ASZ * 2);
            }
            #pragma unroll
            for (int ntp = 0; ntp < 2; ntp++) {
                const int n0 = wn * 32 + ntp * 16;
                const unsigned eb = smem_u32(base + 2 * ASZ
                                             + (kk + (lsel & 1) * 8 + lrow) * BPAD
                                             + n0 + (lsel >> 1) * 8);
                ldsm_x4_t(bh[ntp], eb);
                ldsm_x4_t(bl[ntp], eb + BSZ * 2);
            }
            #pragma unroll
            for (int mt = 0; mt < 4; mt++)
                #pragma unroll
                for (int nt = 0; nt < 4; nt++) {
                    const unsigned* ph = &bh[nt >> 1][(nt & 1) * 2];
                    const unsigned* pl = &bl[nt >> 1][(nt & 1) * 2];
                    mma16816(acc[mt][nt], ah[mt], ph);
                    mma16816(acc[mt][nt], ah[mt], pl);
                    mma16816(acc[mt][nt], al[mt], ph);
                }
        }
        buf ^= 1;
    }

    #pragma unroll
    for (int mt = 0; mt < 4; mt++)
        #pragma unroll
        for (int nt = 0; nt < 4; nt++) {
            const int r  = blockM + wm * 64 + mt * 16 + g;
            const int cc = blockN + wn * 32 + nt * 8 + tg * 2;
            const float v0 = alpha * acc[mt][nt][0];
            const float v1 = alpha * acc[mt][nt][1];
            const float v2 = alpha * acc[mt][nt][2];
            const float v3 = alpha * acc[mt][nt][3];
            if (OUT_SPLIT) {
                unsigned hp, lp;
                split_pack2(v0, v1, hp, lp);
                *(unsigned*)&Ch[(size_t)r * 512 + cc] = hp;
                *(unsigned*)&Cl[(size_t)r * 512 + cc] = lp;
                split_pack2(v2, v3, hp, lp);
                *(unsigned*)&Ch[(size_t)(r + 8) * 512 + cc] = hp;
                *(unsigned*)&Cl[(size_t)(r + 8) * 512 + cc] = lp;
            } else {
                const float b0 = bias[cc], b1 = bias[cc + 1];
                Cf[(size_t)r * 512 + cc]           = v0 + b0;
                Cf[(size_t)r * 512 + cc + 1]       = v1 + b1;
                Cf[(size_t)(r + 8) * 512 + cc]     = v2 + b0;
                Cf[(size_t)(r + 8) * 512 + cc + 1] = v3 + b1;
            }
        }
}

// ----------------------------------------------------------------------------
// Flash attention. K and V staged row-major [64 keys][64+pad dims]; K frags
// via ldmatrix, V^T frags via ldmatrix.trans. S/P in registers, online softmax.
// ----------------------------------------------------------------------------
__global__ __launch_bounds__(256)
void flash_kernel(const __nv_bfloat16* __restrict__ Qh, const __nv_bfloat16* __restrict__ Ql,
                  const __nv_bfloat16* __restrict__ Kh, const __nv_bfloat16* __restrict__ Kl,
                  const __nv_bfloat16* __restrict__ Vh, const __nv_bfloat16* __restrict__ Vl,
                  __nv_bfloat16* __restrict__ Oh, __nv_bfloat16* __restrict__ Ol)
{
    __shared__ __nv_bfloat16 sKh[64][72], sKl[64][72];
    __shared__ __nv_bfloat16 sVh[64][72], sVl[64][72];

    const int z = blockIdx.y;
    const long long zo = z >> 3, zi = z & 7;
    const size_t base = (size_t)zo * 512 * 512 + (size_t)zi * 64;

    const int tid  = threadIdx.x;
    const int lane = tid & 31, warp = tid >> 5;
    const int g = lane >> 2, tg = lane & 3;
    const int lrow = lane & 7, lsel = lane >> 3;
    const int rowA = blockIdx.x * 128 + warp * 16 + g;

    // resident Q fragments
    unsigned qh[4][4], ql[4][4];
    #pragma unroll
    for (int kc = 0; kc < 4; kc++) {
        const int c = kc * 16 + tg * 2;
        qh[kc][0] = *(const unsigned*)&Qh[base + (size_t)rowA * 512 + c];
        qh[kc][1] = *(const unsigned*)&Qh[base + (size_t)(rowA + 8) * 512 + c];
        qh[kc][2] = *(const unsigned*)&Qh[base + (size_t)rowA * 512 + c + 8];
        qh[kc][3] = *(const unsigned*)&Qh[base + (size_t)(rowA + 8) * 512 + c + 8];
        ql[kc][0] = *(const unsigned*)&Ql[base + (size_t)rowA * 512 + c];
        ql[kc][1] = *(const unsigned*)&Ql[base + (size_t)(rowA + 8) * 512 + c];
        ql[kc][2] = *(const unsigned*)&Ql[base + (size_t)rowA * 512 + c + 8];
        ql[kc][3] = *(const unsigned*)&Ql[base + (size_t)(rowA + 8) * 512 + c + 8];
    }

    float o[8][4];
    #pragma unroll
    for (int nd = 0; nd < 8; nd++)
        #pragma unroll
        for (int i = 0; i < 4; i++) o[nd][i] = 0.f;
    float m0 = -1e30f, m1 = -1e30f, l0 = 0.f, l1 = 0.f;

    for (int kt = 0; kt < 8; kt++) {
        #pragma unroll
        for (int j = 0; j < 2; j++) {
            const int idx = tid + j * 256;
            const int row = idx >> 3, q = (idx & 7) * 8;
            const size_t go = base + (size_t)(kt * 64 + row) * 512 + q;
            *(uint4*)&sKh[row][q] = *(const uint4*)(Kh + go);
            *(uint4*)&sKl[row][q] = *(const uint4*)(Kl + go);
            *(uint4*)&sVh[row][q] = *(const uint4*)(Vh + go);
            *(uint4*)&sVl[row][q] = *(const uint4*)(Vl + go);
        }
        __syncthreads();

        // ---- S = Q K^T ----
        float s[8][4];
        #pragma unroll
        for (int nt = 0; nt < 8; nt++)
            #pragma unroll
            for (int i = 0; i < 4; i++) s[nt][i] = 0.f;

        #pragma unroll
        for (int kc = 0; kc < 4; kc++) {
            const int c0 = kc * 16;
            #pragma unroll
            for (int ntp = 0; ntp < 4; ntp++) {
                const int n0 = ntp * 16;
                unsigned bh4[4], bl4[4];
                const unsigned ea = smem_u32(&sKh[n0 + (lsel >> 1) * 8 + lrow][c0 + (lsel & 1) * 8]);
                const unsigned el = smem_u32(&sKl[n0 + (lsel >> 1) * 8 + lrow][c0 + (lsel & 1) * 8]);
                ldsm_x4(bh4, ea);
                ldsm_x4(bl4, el);
                mma16816(s[2 * ntp],     qh[kc], bh4);
                mma16816(s[2 * ntp],     qh[kc], bl4);
                mma16816(s[2 * ntp],     ql[kc], bh4);
                mma16816(s[2 * ntp + 1], qh[kc], bh4 + 2);
                mma16816(s[2 * ntp + 1], qh[kc], bl4 + 2);
                mma16816(s[2 * ntp + 1], ql[kc], bh4 + 2);
            }
        }

        // ---- online softmax ----
        float r0 = -1e30f, r1 = -1e30f;
        #pragma unroll
        for (int nt = 0; nt < 8; nt++) {
            r0 = fmaxf(r0, fmaxf(s[nt][0], s[nt][1]));
            r1 = fmaxf(r1, fmaxf(s[nt][2], s[nt][3]));
        }
        r0 = fmaxf(r0, __shfl_xor_sync(0xffffffffu, r0, 1));
        r0 = fmaxf(r0, __shfl_xor_sync(0xffffffffu, r0, 2));
        r1 = fmaxf(r1, __shfl_xor_sync(0xffffffffu, r1, 1));
        r1 = fmaxf(r1, __shfl_xor_sync(0xffffffffu, r1, 2));
        const float m0n = fmaxf(m0, r0), m1n = fmaxf(m1, r1);
        const float a0 = __expf(m0 - m0n), a1 = __expf(m1 - m1n);

        float ps0 = 0.f, ps1 = 0.f;
        #pragma unroll
        for (int nt = 0; nt < 8; nt++) {
            s[nt][0] = __expf(s[nt][0] - m0n);
            s[nt][1] = __expf(s[nt][1] - m0n);
            s[nt][2] = __expf(s[nt][2] - m1n);
            s[nt][3] = __expf(s[nt][3] - m1n);
            ps0 += s[nt][0] + s[nt][1];
            ps1 += s[nt][2] + s[nt][3];
        }
        m0 = m0n; m1 = m1n;
        l0 = l0 * a0 + ps0;
        l1 = l1 * a1 + ps1;
        #pragma unroll
        for (int nd = 0; nd < 8; nd++) {
            o[nd][0] *= a0; o[nd][1] *= a0;
            o[nd][2] *= a1; o[nd][3] *= a1;
        }

        // ---- O += P V ----
        #pragma unroll
        for (int kc = 0; kc < 4; kc++) {
            const int c0 = kc * 16;
            unsigned pah[4], pal[4];
            split_pack2(s[2 * kc][0],     s[2 * kc][1],     pah[0], pal[0]);
            split_pack2(s[2 * kc][2],     s[2 * kc][3],     pah[1], pal[1]);
            split_pack2(s[2 * kc + 1][0], s[2 * kc + 1][1], pah[2], pal[2]);
            split_pack2(s[2 * kc + 1][2], s[2 * kc + 1][3], pah[3], pal[3]);
            #pragma unroll
            for (int ndp = 0; ndp < 4; ndp++) {
                const int d0 = ndp * 16;
                unsigned vh4[4], vl4[4];
                const unsigned ea = smem_u32(&sVh[c0 + (lsel & 1) * 8 + lrow][d0 + (lsel >> 1) * 8]);
                const unsigned el = smem_u32(&sVl[c0 + (lsel & 1) * 8 + lrow][d0 + (lsel >> 1) * 8]);
                ldsm_x4_t(vh4, ea);
                ldsm_x4_t(vl4, el);
                mma16816(o[2 * ndp],     pah, vh4);
                mma16816(o[2 * ndp],     pah, vl4);
                mma16816(o[2 * ndp],     pal, vh4);
                mma16816(o[2 * ndp + 1], pah, vh4 + 2);
                mma16816(o[2 * ndp + 1], pah, vl4 + 2);
                mma16816(o[2 * ndp + 1], pal, vh4 + 2);
            }
        }
        __syncthreads();
    }

    l0 += __shfl_xor_sync(0xffffffffu, l0, 1);
    l0 += __shfl_xor_sync(0xffffffffu, l0, 2);
    l1 += __shfl_xor_sync(0xffffffffu, l1, 1);
    l1 += __shfl_xor_sync(0xffffffffu, l1, 2);
    const float inv0 = 1.f / l0, inv1 = 1.f / l1;

    #pragma unroll
    for (int nd = 0; nd < 8; nd++) {
        const int cc = nd * 8 + tg * 2;
        unsigned hp, lp;
        split_pack2(o[nd][0] * inv0, o[nd][1] * inv0, hp, lp);
        *(unsigned*)&Oh[base + (size_t)rowA * 512 + cc] = hp;
        *(unsigned*)&Ol[base + (size_t)rowA * 512 + cc] = lp;
        split_pack2(o[nd][2] * inv1, o[nd][3] * inv1, hp, lp);
        *(unsigned*)&Oh[base + (size_t)(rowA + 8) * 512 + cc] = hp;
        *(unsigned*)&Ol[base + (size_t)(rowA + 8) * 512 + cc] = lp;
    }
}

extern "C" void kernel_launch(void* const* d_in, const int* in_sizes, int n_in,
                              void* d_out, int out_size)
{
    const float* q_in  = (const float*)d_in[0];
    const float* kv_in = (const float*)d_in[1];
    const float* Wq    = (const float*)d_in[2];
    const float* Wk    = (const float*)d_in[3];
    const float* Wv    = (const float*)d_in[4];
    const float* Wo    = (const float*)d_in[5];
    const float* bo    = (const float*)d_in[6];
    float* out = (float*)d_out;

    __nv_bfloat16 *qh, *ql, *kvh, *kvl, *wh, *wl;
    __nv_bfloat16 *Qh, *Ql, *Kh, *Kl, *Vh, *Vl, *Oh, *Ol;
    cudaGetSymbolAddress((void**)&qh,  g_qh);  cudaGetSymbolAddress((void**)&ql,  g_ql);
    cudaGetSymbolAddress((void**)&kvh, g_kvh); cudaGetSymbolAddress((void**)&kvl, g_kvl);
    cudaGetSymbolAddress((void**)&wh,  g_wh);  cudaGetSymbolAddress((void**)&wl,  g_wl);
    cudaGetSymbolAddress((void**)&Qh,  g_Qh);  cudaGetSymbolAddress((void**)&Ql,  g_Ql);
    cudaGetSymbolAddress((void**)&Kh,  g_Kh);  cudaGetSymbolAddress((void**)&Kl,  g_Kl);
    cudaGetSymbolAddress((void**)&Vh,  g_Vh);  cudaGetSymbolAddress((void**)&Vl,  g_Vl);
    cudaGetSymbolAddress((void**)&Oh,  g_Oh);  cudaGetSymbolAddress((void**)&Ol,  g_Ol);

    cudaFuncSetAttribute(gemm_bf16_kernel<1>, cudaFuncAttributeMaxDynamicSharedMemorySize, SMEM_DENSE);
    cudaFuncSetAttribute(gemm_bf16_kernel<0>, cudaFuncAttributeMaxDynamicSharedMemorySize, SMEM_DENSE);

    dim3 ggrid(512 / 128, NTOK / 128, 1);

    // launches 1-5: splits (so launch 6 = dense GEMM lands in the ncu -s 5 slot)
    split_kernel<<<(NELEM / 4 + 255) / 256, 256>>>(q_in,  qh,  ql,  NELEM / 4);
    split_kernel<<<(NELEM / 4 + 255) / 256, 256>>>(kv_in, kvh, kvl, NELEM / 4);
    split_kernel<<<(WELEM / 4 + 255) / 256, 256>>>(Wq, wh,             wl,             WELEM / 4);
    split_kernel<<<(WELEM / 4 + 255) / 256, 256>>>(Wk, wh + WELEM,     wl + WELEM,     WELEM / 4);
    split_kernel<<<(WELEM / 4 + 255) / 256, 256>>>(Wv, wh + 2 * WELEM, wl + 2 * WELEM, WELEM / 4);

    // launch 6: profiled dense GEMM (Q projection, pre-scaled by 0.125)
    gemm_bf16_kernel<1><<<ggrid, 256, SMEM_DENSE>>>(qh, ql, wh, wl, nullptr, Qh, Ql, nullptr, 0.125f);

    split_kernel<<<(WELEM / 4 + 255) / 256, 256>>>(Wo, wh + 3 * WELEM, wl + 3 * WELEM, WELEM / 4);

    gemm_bf16_kernel<1><<<ggrid, 256, SMEM_DENSE>>>(kvh, kvl, wh + WELEM,     wl + WELEM,     nullptr, Kh, Kl, nullptr, 1.f);
    gemm_bf16_kernel<1><<<ggrid, 256, SMEM_DENSE>>>(kvh, kvl, wh + 2 * WELEM, wl + 2 * WELEM, nullptr, Vh, Vl, nullptr, 1.f);

    flash_kernel<<<dim3(4, 256), 256>>>(Qh, Ql, Kh, Kl, Vh, Vl, Oh, Ol);

    gemm_bf16_kernel<0><<<ggrid, 256, SMEM_DENSE>>>(Oh, Ol, wh + 3 * WELEM, wl + 3 * WELEM, out, nullptr, nullptr, bo, 1.f);
}

// round 4
// speedup vs baseline: 1.9715x; 1.0056x over previous
#include <cuda_runtime.h>
#include <cuda_bf16.h>
#include <cstdint>

// ----------------------------------------------------------------------------
// CrossAttention: split-bf16 (3-MMA) everywhere; flash-fused attention.
// This round: 128x128 dense GEMM tiles, ldmatrix fragment loads, cp.async
// double-buffered pipeline; flash uses ldmatrix + trans-ldmatrix for V.
// ----------------------------------------------------------------------------

namespace {
constexpr int NTOK = 16384;
constexpr int DMODEL = 512;
constexpr int NELEM = NTOK * DMODEL;
constexpr int WELEM = DMODEL * DMODEL;

// dense smem layout (elements)
constexpr int APAD = 40;                 // 80B row stride: conflict-free ldsm
constexpr int BPAD = 136;                // 272B row stride: conflict-free ldsm
constexpr int ASZ = 128 * APAD;          // 5120
constexpr int BSZ = 32 * BPAD;           // 4352
constexpr int STG = 2 * ASZ + 2 * BSZ;   // 18944 elements per stage
constexpr int SMEM_DENSE = 2 * STG * 2;  // bytes = 75776
}

__device__ __nv_bfloat16 g_qh[NELEM],  g_ql[NELEM];
__device__ __nv_bfloat16 g_kvh[NELEM], g_kvl[NELEM];
__device__ __nv_bfloat16 g_wh[4 * WELEM], g_wl[4 * WELEM];
__device__ __nv_bfloat16 g_Qh[NELEM], g_Ql[NELEM];
__device__ __nv_bfloat16 g_Kh[NELEM], g_Kl[NELEM];
__device__ __nv_bfloat16 g_Vh[NELEM], g_Vl[NELEM];
__device__ __nv_bfloat16 g_Oh[NELEM], g_Ol[NELEM];

__device__ __forceinline__ void mma16816(float* d, const unsigned* a, const unsigned* b) {
    asm volatile(
        "mma.sync.aligned.m16n8k16.row.col.f32.bf16.bf16.f32 "
        "{%0,%1,%2,%3},{%4,%5,%6,%7},{%8,%9},{%0,%1,%2,%3};\n"
        : "+f"(d[0]), "+f"(d[1]), "+f"(d[2]), "+f"(d[3])
        : "r"(a[0]), "r"(a[1]), "r"(a[2]), "r"(a[3]), "r"(b[0]), "r"(b[1]));
}

__device__ __forceinline__ unsigned smem_u32(const void* p) {
    return (unsigned)__cvta_generic_to_shared(p);
}
__device__ __forceinline__ void ldsm_x4(unsigned* r, unsigned addr) {
    asm volatile("ldmatrix.sync.aligned.m8n8.x4.shared.b16 {%0,%1,%2,%3}, [%4];"
                 : "=r"(r[0]), "=r"(r[1]), "=r"(r[2]), "=r"(r[3]) : "r"(addr));
}
__device__ __forceinline__ void ldsm_x4_t(unsigned* r, unsigned addr) {
    asm volatile("ldmatrix.sync.aligned.m8n8.x4.trans.shared.b16 {%0,%1,%2,%3}, [%4];"
                 : "=r"(r[0]), "=r"(r[1]), "=r"(r[2]), "=r"(r[3]) : "r"(addr));
}
__device__ __forceinline__ void cp16(unsigned dst, const void* src) {
    asm volatile("cp.async.cg.shared.global [%0], [%1], 16;\n" :: "r"(dst), "l"(src));
}
__device__ __forceinline__ void cp_commit() { asm volatile("cp.async.commit_group;\n" ::: "memory"); }
__device__ __forceinline__ void cp_wait0()  { asm volatile("cp.async.wait_group 0;\n" ::: "memory"); }

__device__ __forceinline__ unsigned pack2(__nv_bfloat16 x, __nv_bfloat16 y) {
    __nv_bfloat162 t{x, y};
    return *reinterpret_cast<unsigned*>(&t);
}
__device__ __forceinline__ void split_pack2(float x, float y, unsigned& hp, unsigned& lp) {
    __nv_bfloat16 hx = __float2bfloat16(x), hy = __float2bfloat16(y);
    __nv_bfloat16 lx = __float2bfloat16(x - __bfloat162float(hx));
    __nv_bfloat16 ly = __float2bfloat16(y - __bfloat162float(hy));
    hp = pack2(hx, hy);
    lp = pack2(lx, ly);
}

__global__ __launch_bounds__(256)
void split_kernel(const float* __restrict__ src, __nv_bfloat16* __restrict__ dh,
                  __nv_bfloat16* __restrict__ dl, int n4)
{
    int i = blockIdx.x * blockDim.x + threadIdx.x;
    if (i >= n4) return;
    float4 v = reinterpret_cast<const float4*>(src)[i];
    unsigned h01, l01, h23, l23;
    split_pack2(v.x, v.y, h01, l01);
    split_pack2(v.z, v.w, h23, l23);
    uint2 hv{h01, h23}, lv{l01, l23};
    reinterpret_cast<uint2*>(dh)[i] = hv;
    reinterpret_cast<uint2*>(dl)[i] = lv;
}

// ----------------------------------------------------------------------------
// Dense GEMM: C = alpha * A @ B (+bias). A [16384 x 512] row-major split bf16,
// B [512 x 512] row-major split bf16 (loaded via trans-ldmatrix).
// CTA tile 128x128, BK=32, 8 warps (2x4), double-buffered cp.async.
// ----------------------------------------------------------------------------
template <int OUT_SPLIT>
__global__ __launch_bounds__(256)
void gemm_bf16_kernel(const __nv_bfloat16* __restrict__ Ah, const __nv_bfloat16* __restrict__ Al,
                      const __nv_bfloat16* __restrict__ Bh, const __nv_bfloat16* __restrict__ Bl,
                      float* __restrict__ Cf,
                      __nv_bfloat16* __restrict__ Ch, __nv_bfloat16* __restrict__ Cl,
                      const float* __restrict__ bias, float alpha)
{
    extern __shared__ __nv_bfloat16 sm[];

    const int tid  = threadIdx.x;
    const int lane = tid & 31, warp = tid >> 5;
    const int wm = warp >> 2, wn = warp & 3;          // 2x4 warp grid, 64x32 tiles
    const int g  = lane >> 2, tg = lane & 3;
    const int lrow = lane & 7, lsel = lane >> 3;
    const int blockM = blockIdx.y * 128, blockN = blockIdx.x * 128;

    // cp.async per-thread coordinates
    const int arow = tid >> 2, acol = (tid & 3) * 8;  // A: rows arow + j*64
    const int brow = tid >> 4, bcol = (tid & 15) * 8; // B: rows brow + j*16

    float acc[4][4][4];
    #pragma unroll
    for (int mt = 0; mt < 4; mt++)
        #pragma unroll
        for (int nt = 0; nt < 4; nt++)
            #pragma unroll
            for (int i = 0; i < 4; i++) acc[mt][nt][i] = 0.f;

    auto load_tile = [&](int kt, int s) {
        __nv_bfloat16* base = sm + s * STG;
        #pragma unroll
        for (int j = 0; j < 2; j++) {
            const int r = arow + j * 64;
            const size_t go = (size_t)(blockM + r) * 512 + kt * 32 + acol;
            cp16(smem_u32(base + r * APAD + acol),             Ah + go);
            cp16(smem_u32(base + ASZ + r * APAD + acol),       Al + go);
        }
        #pragma unroll
        for (int j = 0; j < 2; j++) {
            const int k = brow + j * 16;
            const size_t go = (size_t)(kt * 32 + k) * 512 + blockN + bcol;
            cp16(smem_u32(base + 2 * ASZ + k * BPAD + bcol),       Bh + go);
            cp16(smem_u32(base + 2 * ASZ + BSZ + k * BPAD + bcol), Bl + go);
        }
    };

    load_tile(0, 0);
    cp_commit();

    int buf = 0;
    for (int kt = 0; kt < 16; kt++) {
        cp_wait0();
        __syncthreads();
        if (kt < 15) { load_tile(kt + 1, buf ^ 1); cp_commit(); }

        const __nv_bfloat16* base = sm + buf * STG;
        #pragma unroll
        for (int kk = 0; kk < 32; kk += 16) {
            unsigned ah[4][4], al[4][4], bh[2][4], bl[2][4];
            #pragma unroll
            for (int mt = 0; mt < 4; mt++) {
                const int r0 = wm * 64 + mt * 16;
                const unsigned ea = smem_u32(base + (r0 + (lsel & 1) * 8 + lrow) * APAD
                                             + kk + (lsel >> 1) * 8);
                ldsm_x4(ah[mt], ea);
                ldsm_x4(al[mt], ea + ASZ * 2);
            }
            #pragma unroll
            for (int ntp = 0; ntp < 2; ntp++) {
                const int n0 = wn * 32 + ntp * 16;
                const unsigned eb = smem_u32(base + 2 * ASZ
                                             + (kk + (lsel & 1) * 8 + lrow) * BPAD
                                             + n0 + (lsel >> 1) * 8);
                ldsm_x4_t(bh[ntp], eb);
                ldsm_x4_t(bl[ntp], eb + BSZ * 2);
            }
            #pragma unroll
            for (int mt = 0; mt < 4; mt++)
                #pragma unroll
                for (int nt = 0; nt < 4; nt++) {
                    const unsigned* ph = &bh[nt >> 1][(nt & 1) * 2];
                    const unsigned* pl = &bl[nt >> 1][(nt & 1) * 2];
                    mma16816(acc[mt][nt], ah[mt], ph);
                    mma16816(acc[mt][nt], ah[mt], pl);
                    mma16816(acc[mt][nt], al[mt], ph);
                }
        }
        buf ^= 1;
    }

    #pragma unroll
    for (int mt = 0; mt < 4; mt++)
        #pragma unroll
        for (int nt = 0; nt < 4; nt++) {
            const int r  = blockM + wm * 64 + mt * 16 + g;
            const int cc = blockN + wn * 32 + nt * 8 + tg * 2;
            const float v0 = alpha * acc[mt][nt][0];
            const float v1 = alpha * acc[mt][nt][1];
            const float v2 = alpha * acc[mt][nt][2];
            const float v3 = alpha * acc[mt][nt][3];
            if (OUT_SPLIT) {
                unsigned hp, lp;
                split_pack2(v0, v1, hp, lp);
                *(unsigned*)&Ch[(size_t)r * 512 + cc] = hp;
                *(unsigned*)&Cl[(size_t)r * 512 + cc] = lp;
                split_pack2(v2, v3, hp, lp);
                *(unsigned*)&Ch[(size_t)(r + 8) * 512 + cc] = hp;
                *(unsigned*)&Cl[(size_t)(r + 8) * 512 + cc] = lp;
            } else {
                const float b0 = bias[cc], b1 = bias[cc + 1];
                Cf[(size_t)r * 512 + cc]           = v0 + b0;
                Cf[(size_t)r * 512 + cc + 1]       = v1 + b1;
                Cf[(size_t)(r + 8) * 512 + cc]     = v2 + b0;
                Cf[(size_t)(r + 8) * 512 + cc + 1] = v3 + b1;
            }
        }
}

// ----------------------------------------------------------------------------
// Flash attention. K and V staged row-major [64 keys][64+pad dims]; K frags
// via ldmatrix, V^T frags via ldmatrix.trans. S/P in registers, online softmax.
// ----------------------------------------------------------------------------
__global__ __launch_bounds__(256)
void flash_kernel(const __nv_bfloat16* __restrict__ Qh, const __nv_bfloat16* __restrict__ Ql,
                  const __nv_bfloat16* __restrict__ Kh, const __nv_bfloat16* __restrict__ Kl,
                  const __nv_bfloat16* __restrict__ Vh, const __nv_bfloat16* __restrict__ Vl,
                  __nv_bfloat16* __restrict__ Oh, __nv_bfloat16* __restrict__ Ol)
{
    __shared__ __nv_bfloat16 sKh[64][72], sKl[64][72];
    __shared__ __nv_bfloat16 sVh[64][72], sVl[64][72];

    const int z = blockIdx.y;
    const long long zo = z >> 3, zi = z & 7;
    const size_t base = (size_t)zo * 512 * 512 + (size_t)zi * 64;

    const int tid  = threadIdx.x;
    const int lane = tid & 31, warp = tid >> 5;
    const int g = lane >> 2, tg = lane & 3;
    const int lrow = lane & 7, lsel = lane >> 3;
    const int rowA = blockIdx.x * 128 + warp * 16 + g;

    // resident Q fragments
    unsigned qh[4][4], ql[4][4];
    #pragma unroll
    for (int kc = 0; kc < 4; kc++) {
        const int c = kc * 16 + tg * 2;
        qh[kc][0] = *(const unsigned*)&Qh[base + (size_t)rowA * 512 + c];
        qh[kc][1] = *(const unsigned*)&Qh[base + (size_t)(rowA + 8) * 512 + c];
        qh[kc][2] = *(const unsigned*)&Qh[base + (size_t)rowA * 512 + c + 8];
        qh[kc][3] = *(const unsigned*)&Qh[base + (size_t)(rowA + 8) * 512 + c + 8];
        ql[kc][0] = *(const unsigned*)&Ql[base + (size_t)rowA * 512 + c];
        ql[kc][1] = *(const unsigned*)&Ql[base + (size_t)(rowA + 8) * 512 + c];
        ql[kc][2] = *(const unsigned*)&Ql[base + (size_t)rowA * 512 + c + 8];
        ql[kc][3] = *(const unsigned*)&Ql[base + (size_t)(rowA + 8) * 512 + c + 8];
    }

    float o[8][4];
    #pragma unroll
    for (int nd = 0; nd < 8; nd++)
        #pragma unroll
        for (int i = 0; i < 4; i++) o[nd][i] = 0.f;
    float m0 = -1e30f, m1 = -1e30f, l0 = 0.f, l1 = 0.f;

    for (int kt = 0; kt < 8; kt++) {
        #pragma unroll
        for (int j = 0; j < 2; j++) {
            const int idx = tid + j * 256;
            const int row = idx >> 3, q = (idx & 7) * 8;
            const size_t go = base + (size_t)(kt * 64 + row) * 512 + q;
            *(uint4*)&sKh[row][q] = *(const uint4*)(Kh + go);
            *(uint4*)&sKl[row][q] = *(const uint4*)(Kl + go);
            *(uint4*)&sVh[row][q] = *(const uint4*)(Vh + go);
            *(uint4*)&sVl[row][q] = *(const uint4*)(Vl + go);
        }
        __syncthreads();

        // ---- S = Q K^T ----
        float s[8][4];
        #pragma unroll
        for (int nt = 0; nt < 8; nt++)
            #pragma unroll
            for (int i = 0; i < 4; i++) s[nt][i] = 0.f;

        #pragma unroll
        for (int kc = 0; kc < 4; kc++) {
            const int c0 = kc * 16;
            #pragma unroll
            for (int ntp = 0; ntp < 4; ntp++) {
                const int n0 = ntp * 16;
                unsigned bh4[4], bl4[4];
                const unsigned ea = smem_u32(&sKh[n0 + (lsel >> 1) * 8 + lrow][c0 + (lsel & 1) * 8]);
                const unsigned el = smem_u32(&sKl[n0 + (lsel >> 1) * 8 + lrow][c0 + (lsel & 1) * 8]);
                ldsm_x4(bh4, ea);
                ldsm_x4(bl4, el);
                mma16816(s[2 * ntp],     qh[kc], bh4);
                mma16816(s[2 * ntp],     qh[kc], bl4);
                mma16816(s[2 * ntp],     ql[kc], bh4);
                mma16816(s[2 * ntp + 1], qh[kc], bh4 + 2);
                mma16816(s[2 * ntp + 1], qh[kc], bl4 + 2);
                mma16816(s[2 * ntp + 1], ql[kc], bh4 + 2);
            }
        }

        // ---- online softmax ----
        float r0 = -1e30f, r1 = -1e30f;
        #pragma unroll
        for (int nt = 0; nt < 8; nt++) {
            r0 = fmaxf(r0, fmaxf(s[nt][0], s[nt][1]));
            r1 = fmaxf(r1, fmaxf(s[nt][2], s[nt][3]));
        }
        r0 = fmaxf(r0, __shfl_xor_sync(0xffffffffu, r0, 1));
        r0 = fmaxf(r0, __shfl_xor_sync(0xffffffffu, r0, 2));
        r1 = fmaxf(r1, __shfl_xor_sync(0xffffffffu, r1, 1));
        r1 = fmaxf(r1, __shfl_xor_sync(0xffffffffu, r1, 2));
        const float m0n = fmaxf(m0, r0), m1n = fmaxf(m1, r1);
        const float a0 = __expf(m0 - m0n), a1 = __expf(m1 - m1n);

        float ps0 = 0.f, ps1 = 0.f;
        #pragma unroll
        for (int nt = 0; nt < 8; nt++) {
            s[nt][0] = __expf(s[nt][0] - m0n);
            s[nt][1] = __expf(s[nt][1] - m0n);
            s[nt][2] = __expf(s[nt][2] - m1n);
            s[nt][3] = __expf(s[nt][3] - m1n);
            ps0 += s[nt][0] + s[nt][1];
            ps1 += s[nt][2] + s[nt][3];
        }
        m0 = m0n; m1 = m1n;
        l0 = l0 * a0 + ps0;
        l1 = l1 * a1 + ps1;
        #pragma unroll
        for (int nd = 0; nd < 8; nd++) {
            o[nd][0] *= a0; o[nd][1] *= a0;
            o[nd][2] *= a1; o[nd][3] *= a1;
        }

        // ---- O += P V ----
        #pragma unroll
        for (int kc = 0; kc < 4; kc++) {
            const int c0 = kc * 16;
            unsigned pah[4], pal[4];
            split_pack2(s[2 * kc][0],     s[2 * kc][1],     pah[0], pal[0]);
            split_pack2(s[2 * kc][2],     s[2 * kc][3],     pah[1], pal[1]);
            split_pack2(s[2 * kc + 1][0], s[2 * kc + 1][1], pah[2], pal[2]);
            split_pack2(s[2 * kc + 1][2], s[2 * kc + 1][3], pah[3], pal[3]);
            #pragma unroll
            for (int ndp = 0; ndp < 4; ndp++) {
                const int d0 = ndp * 16;
                unsigned vh4[4], vl4[4];
                const unsigned ea = smem_u32(&sVh[c0 + (lsel & 1) * 8 + lrow][d0 + (lsel >> 1) * 8]);
                const unsigned el = smem_u32(&sVl[c0 + (lsel & 1) * 8 + lrow][d0 + (lsel >> 1) * 8]);
                ldsm_x4_t(vh4, ea);
                ldsm_x4_t(vl4, el);
                mma16816(o[2 * ndp],     pah, vh4);
                mma16816(o[2 * ndp],     pah, vl4);
                mma16816(o[2 * ndp],     pal, vh4);
                mma16816(o[2 * ndp + 1], pah, vh4 + 2);
                mma16816(o[2 * ndp + 1], pah, vl4 + 2);
                mma16816(o[2 * ndp + 1], pal, vh4 + 2);
            }
        }
        __syncthreads();
    }

    l0 += __shfl_xor_sync(0xffffffffu, l0, 1);
    l0 += __shfl_xor_sync(0xffffffffu, l0, 2);
    l1 += __shfl_xor_sync(0xffffffffu, l1, 1);
    l1 += __shfl_xor_sync(0xffffffffu, l1, 2);
    const float inv0 = 1.f / l0, inv1 = 1.f / l1;

    #pragma unroll
    for (int nd = 0; nd < 8; nd++) {
        const int cc = nd * 8 + tg * 2;
        unsigned hp, lp;
        split_pack2(o[nd][0] * inv0, o[nd][1] * inv0, hp, lp);
        *(unsigned*)&Oh[base + (size_t)rowA * 512 + cc] = hp;
        *(unsigned*)&Ol[base + (size_t)rowA * 512 + cc] = lp;
        split_pack2(o[nd][2] * inv1, o[nd][3] * inv1, hp, lp);
        *(unsigned*)&Oh[base + (size_t)(rowA + 8) * 512 + cc] = hp;
        *(unsigned*)&Ol[base + (size_t)(rowA + 8) * 512 + cc] = lp;
    }
}

extern "C" void kernel_launch(void* const* d_in, const int* in_sizes, int n_in,
                              void* d_out, int out_size)
{
    const float* q_in  = (const float*)d_in[0];
    const float* kv_in = (const float*)d_in[1];
    const float* Wq    = (const float*)d_in[2];
    const float* Wk    = (const float*)d_in[3];
    const float* Wv    = (const float*)d_in[4];
    const float* Wo    = (const float*)d_in[5];
    const float* bo    = (const float*)d_in[6];
    float* out = (float*)d_out;

    __nv_bfloat16 *qh, *ql, *kvh, *kvl, *wh, *wl;
    __nv_bfloat16 *Qh, *Ql, *Kh, *Kl, *Vh, *Vl, *Oh, *Ol;
    cudaGetSymbolAddress((void**)&qh,  g_qh);  cudaGetSymbolAddress((void**)&ql,  g_ql);
    cudaGetSymbolAddress((void**)&kvh, g_kvh); cudaGetSymbolAddress((void**)&kvl, g_kvl);
    cudaGetSymbolAddress((void**)&wh,  g_wh);  cudaGetSymbolAddress((void**)&wl,  g_wl);
    cudaGetSymbolAddress((void**)&Qh,  g_Qh);  cudaGetSymbolAddress((void**)&Ql,  g_Ql);
    cudaGetSymbolAddress((void**)&Kh,  g_Kh);  cudaGetSymbolAddress((void**)&Kl,  g_Kl);
    cudaGetSymbolAddress((void**)&Vh,  g_Vh);  cudaGetSymbolAddress((void**)&Vl,  g_Vl);
    cudaGetSymbolAddress((void**)&Oh,  g_Oh);  cudaGetSymbolAddress((void**)&Ol,  g_Ol);

    cudaFuncSetAttribute(gemm_bf16_kernel<1>, cudaFuncAttributeMaxDynamicSharedMemorySize, SMEM_DENSE);
    cudaFuncSetAttribute(gemm_bf16_kernel<0>, cudaFuncAttributeMaxDynamicSharedMemorySize, SMEM_DENSE);

    dim3 ggrid(512 / 128, NTOK / 128, 1);

    // launches 1-5: splits (so launch 6 = dense GEMM lands in the ncu -s 5 slot)
    split_kernel<<<(NELEM / 4 + 255) / 256, 256>>>(q_in,  qh,  ql,  NELEM / 4);
    split_kernel<<<(NELEM / 4 + 255) / 256, 256>>>(kv_in, kvh, kvl, NELEM / 4);
    split_kernel<<<(WELEM / 4 + 255) / 256, 256>>>(Wq, wh,             wl,             WELEM / 4);
    split_kernel<<<(WELEM / 4 + 255) / 256, 256>>>(Wk, wh + WELEM,     wl + WELEM,     WELEM / 4);
    split_kernel<<<(WELEM / 4 + 255) / 256, 256>>>(Wv, wh + 2 * WELEM, wl + 2 * WELEM, WELEM / 4);

    // launch 6: profiled dense GEMM (Q projection, pre-scaled by 0.125)
    gemm_bf16_kernel<1><<<ggrid, 256, SMEM_DENSE>>>(qh, ql, wh, wl, nullptr, Qh, Ql, nullptr, 0.125f);

    split_kernel<<<(WELEM / 4 + 255) / 256, 256>>>(Wo, wh + 3 * WELEM, wl + 3 * WELEM, WELEM / 4);

    gemm_bf16_kernel<1><<<ggrid, 256, SMEM_DENSE>>>(kvh, kvl, wh + WELEM,     wl + WELEM,     nullptr, Kh, Kl, nullptr, 1.f);
    gemm_bf16_kernel<1><<<ggrid, 256, SMEM_DENSE>>>(kvh, kvl, wh + 2 * WELEM, wl + 2 * WELEM, nullptr, Vh, Vl, nullptr, 1.f);

    flash_kernel<<<dim3(4, 256), 256>>>(Qh, Ql, Kh, Kl, Vh, Vl, Oh, Ol);

    gemm_bf16_kernel<0><<<ggrid, 256, SMEM_DENSE>>>(Oh, Ol, wh + 3 * WELEM, wl + 3 * WELEM, out, nullptr, nullptr, bo, 1.f);
}

// round 6
// speedup vs baseline: 2.1673x; 1.0993x over previous
#include <cuda_runtime.h>
#include <cuda_bf16.h>
#include <cstdint>

// ----------------------------------------------------------------------------
// CrossAttention: split-bf16 (3-MMA) on mma.sync HMMA everywhere (tcgen05 is
// rejected by this harness's ptxas target). Flash attention now uses a
// cp.async double-buffered K/V pipeline.
// ----------------------------------------------------------------------------

namespace {
constexpr int NTOK = 16384;
constexpr int DMODEL = 512;
constexpr int NELEM = NTOK * DMODEL;
constexpr int WELEM = DMODEL * DMODEL;

// dense smem layout (elements)
constexpr int APAD = 40;
constexpr int BPAD = 136;
constexpr int ASZ = 128 * APAD;
constexpr int BSZ = 32 * BPAD;
constexpr int STG = 2 * ASZ + 2 * BSZ;
constexpr int SMEM_DENSE = 2 * STG * 2;          // 75776 bytes

// flash smem: stage = sKh|sKl|sVh|sVl, each [64][72]
constexpr int FARR = 64 * 72;                    // 4608 elements
constexpr int FSTG = 4 * FARR;                   // 18432 elements
constexpr int SMEM_FLASH = 2 * FSTG * 2;         // 73728 bytes
}

__device__ __nv_bfloat16 g_qh[NELEM],  g_ql[NELEM];
__device__ __nv_bfloat16 g_kvh[NELEM], g_kvl[NELEM];
__device__ __nv_bfloat16 g_wh[4 * WELEM], g_wl[4 * WELEM];
__device__ __nv_bfloat16 g_Qh[NELEM], g_Ql[NELEM];
__device__ __nv_bfloat16 g_Kh[NELEM], g_Kl[NELEM];
__device__ __nv_bfloat16 g_Vh[NELEM], g_Vl[NELEM];
__device__ __nv_bfloat16 g_Oh[NELEM], g_Ol[NELEM];

__device__ __forceinline__ void mma16816(float* d, const unsigned* a, const unsigned* b) {
    asm volatile(
        "mma.sync.aligned.m16n8k16.row.col.f32.bf16.bf16.f32 "
        "{%0,%1,%2,%3},{%4,%5,%6,%7},{%8,%9},{%0,%1,%2,%3};\n"
        : "+f"(d[0]), "+f"(d[1]), "+f"(d[2]), "+f"(d[3])
        : "r"(a[0]), "r"(a[1]), "r"(a[2]), "r"(a[3]), "r"(b[0]), "r"(b[1]));
}
__device__ __forceinline__ unsigned smem_u32(const void* p) {
    return (unsigned)__cvta_generic_to_shared(p);
}
__device__ __forceinline__ void ldsm_x4(unsigned* r, unsigned addr) {
    asm volatile("ldmatrix.sync.aligned.m8n8.x4.shared.b16 {%0,%1,%2,%3}, [%4];"
                 : "=r"(r[0]), "=r"(r[1]), "=r"(r[2]), "=r"(r[3]) : "r"(addr));
}
__device__ __forceinline__ void ldsm_x4_t(unsigned* r, unsigned addr) {
    asm volatile("ldmatrix.sync.aligned.m8n8.x4.trans.shared.b16 {%0,%1,%2,%3}, [%4];"
                 : "=r"(r[0]), "=r"(r[1]), "=r"(r[2]), "=r"(r[3]) : "r"(addr));
}
__device__ __forceinline__ void cp16(unsigned dst, const void* src) {
    asm volatile("cp.async.cg.shared.global [%0], [%1], 16;\n" :: "r"(dst), "l"(src));
}
__device__ __forceinline__ void cp_commit() { asm volatile("cp.async.commit_group;\n" ::: "memory"); }
__device__ __forceinline__ void cp_wait0()  { asm volatile("cp.async.wait_group 0;\n" ::: "memory"); }
__device__ __forceinline__ void cp_wait1()  { asm volatile("cp.async.wait_group 1;\n" ::: "memory"); }

__device__ __forceinline__ unsigned pack2(__nv_bfloat16 x, __nv_bfloat16 y) {
    __nv_bfloat162 t{x, y};
    return *reinterpret_cast<unsigned*>(&t);
}
__device__ __forceinline__ void split_pack2(float x, float y, unsigned& hp, unsigned& lp) {
    __nv_bfloat16 hx = __float2bfloat16(x), hy = __float2bfloat16(y);
    __nv_bfloat16 lx = __float2bfloat16(x - __bfloat162float(hx));
    __nv_bfloat16 ly = __float2bfloat16(y - __bfloat162float(hy));
    hp = pack2(hx, hy);
    lp = pack2(lx, ly);
}

// ---- fp32 -> (hi, lo) bf16 split, vectorized ----
__global__ __launch_bounds__(256)
void split_kernel(const float* __restrict__ src, __nv_bfloat16* __restrict__ dh,
                  __nv_bfloat16* __restrict__ dl, int n4)
{
    int i = blockIdx.x * blockDim.x + threadIdx.x;
    if (i >= n4) return;
    float4 v = reinterpret_cast<const float4*>(src)[i];
    unsigned h01, l01, h23, l23;
    split_pack2(v.x, v.y, h01, l01);
    split_pack2(v.z, v.w, h23, l23);
    uint2 hv{h01, h23}, lv{l01, l23};
    reinterpret_cast<uint2*>(dh)[i] = hv;
    reinterpret_cast<uint2*>(dl)[i] = lv;
}

// all 4 weights split in one launch; z selects the weight
__global__ __launch_bounds__(256)
void split4_kernel(const float* __restrict__ W0, const float* __restrict__ W1,
                   const float* __restrict__ W2, const float* __restrict__ W3,
                   __nv_bfloat16* __restrict__ dh, __nv_bfloat16* __restrict__ dl)
{
    const int z = blockIdx.z;
    const float* src = (z == 0) ? W0 : (z == 1) ? W1 : (z == 2) ? W2 : W3;
    __nv_bfloat16* h = dh + (size_t)z * WELEM;
    __nv_bfloat16* l = dl + (size_t)z * WELEM;
    int i = blockIdx.x * blockDim.x + threadIdx.x;
    if (i >= WELEM / 4) return;
    float4 v = reinterpret_cast<const float4*>(src)[i];
    unsigned h01, l01, h23, l23;
    split_pack2(v.x, v.y, h01, l01);
    split_pack2(v.z, v.w, h23, l23);
    uint2 hv{h01, h23}, lv{l01, l23};
    reinterpret_cast<uint2*>(h)[i] = hv;
    reinterpret_cast<uint2*>(l)[i] = lv;
}

// ----------------------------------------------------------------------------
// Dense GEMM (proven R4 version): C = alpha*A@B (+bias). 128x128 tile, BK=32,
// 8 warps (2x4), cp.async double buffer, ldmatrix fragments.
// ----------------------------------------------------------------------------
template <int OUT_SPLIT>
__global__ __launch_bounds__(256)
void gemm_bf16_kernel(const __nv_bfloat16* __restrict__ Ah, const __nv_bfloat16* __restrict__ Al,
                      const __nv_bfloat16* __restrict__ Bh, const __nv_bfloat16* __restrict__ Bl,
                      float* __restrict__ Cf,
                      __nv_bfloat16* __restrict__ Ch, __nv_bfloat16* __restrict__ Cl,
                      const float* __restrict__ bias, float alpha)
{
    extern __shared__ __nv_bfloat16 sm[];

    const int tid  = threadIdx.x;
    const int lane = tid & 31, warp = tid >> 5;
    const int wm = warp >> 2, wn = warp & 3;
    const int g  = lane >> 2, tg = lane & 3;
    const int lrow = lane & 7, lsel = lane >> 3;
    const int blockM = blockIdx.y * 128, blockN = blockIdx.x * 128;

    const int arow = tid >> 2, acol = (tid & 3) * 8;
    const int brow = tid >> 4, bcol = (tid & 15) * 8;

    float acc[4][4][4];
    #pragma unroll
    for (int mt = 0; mt < 4; mt++)
        #pragma unroll
        for (int nt = 0; nt < 4; nt++)
            #pragma unroll
            for (int i = 0; i < 4; i++) acc[mt][nt][i] = 0.f;

    auto load_tile = [&](int kt, int s) {
        __nv_bfloat16* base = sm + s * STG;
        #pragma unroll
        for (int j = 0; j < 2; j++) {
            const int r = arow + j * 64;
            const size_t go = (size_t)(blockM + r) * 512 + kt * 32 + acol;
            cp16(smem_u32(base + r * APAD + acol),       Ah + go);
            cp16(smem_u32(base + ASZ + r * APAD + acol), Al + go);
        }
        #pragma unroll
        for (int j = 0; j < 2; j++) {
            const int k = brow + j * 16;
            const size_t go = (size_t)(kt * 32 + k) * 512 + blockN + bcol;
            cp16(smem_u32(base + 2 * ASZ + k * BPAD + bcol),       Bh + go);
            cp16(smem_u32(base + 2 * ASZ + BSZ + k * BPAD + bcol), Bl + go);
        }
    };

    load_tile(0, 0);
    cp_commit();

    int buf = 0;
    for (int kt = 0; kt < 16; kt++) {
        cp_wait0();
        __syncthreads();
        if (kt < 15) { load_tile(kt + 1, buf ^ 1); cp_commit(); }

        const __nv_bfloat16* base = sm + buf * STG;
        #pragma unroll
        for (int kk = 0; kk < 32; kk += 16) {
            unsigned ah[4][4], al[4][4], bh[2][4], bl[2][4];
            #pragma unroll
            for (int mt = 0; mt < 4; mt++) {
                const int r0 = wm * 64 + mt * 16;
                const unsigned ea = smem_u32(base + (r0 + (lsel & 1) * 8 + lrow) * APAD
                                             + kk + (lsel >> 1) * 8);
                ldsm_x4(ah[mt], ea);
                ldsm_x4(al[mt], ea + ASZ * 2);
            }
            #pragma unroll
            for (int ntp = 0; ntp < 2; ntp++) {
                const int n0 = wn * 32 + ntp * 16;
                const unsigned eb = smem_u32(base + 2 * ASZ
                                             + (kk + (lsel & 1) * 8 + lrow) * BPAD
                                             + n0 + (lsel >> 1) * 8);
                ldsm_x4_t(bh[ntp], eb);
                ldsm_x4_t(bl[ntp], eb + BSZ * 2);
            }
            #pragma unroll
            for (int mt = 0; mt < 4; mt++)
                #pragma unroll
                for (int nt = 0; nt < 4; nt++) {
                    const unsigned* ph = &bh[nt >> 1][(nt & 1) * 2];
                    const unsigned* pl = &bl[nt >> 1][(nt & 1) * 2];
                    mma16816(acc[mt][nt], ah[mt], ph);
                    mma16816(acc[mt][nt], ah[mt], pl);
                    mma16816(acc[mt][nt], al[mt], ph);
                }
        }
        buf ^= 1;
    }

    #pragma unroll
    for (int mt = 0; mt < 4; mt++)
        #pragma unroll
        for (int nt = 0; nt < 4; nt++) {
            const int r  = blockM + wm * 64 + mt * 16 + g;
            const int cc = blockN + wn * 32 + nt * 8 + tg * 2;
            const float v0 = alpha * acc[mt][nt][0];
            const float v1 = alpha * acc[mt][nt][1];
            const float v2 = alpha * acc[mt][nt][2];
            const float v3 = alpha * acc[mt][nt][3];
            if (OUT_SPLIT) {
                unsigned hp, lp;
                split_pack2(v0, v1, hp, lp);
                *(unsigned*)&Ch[(size_t)r * 512 + cc] = hp;
                *(unsigned*)&Cl[(size_t)r * 512 + cc] = lp;
                split_pack2(v2, v3, hp, lp);
                *(unsigned*)&Ch[(size_t)(r + 8) * 512 + cc] = hp;
                *(unsigned*)&Cl[(size_t)(r + 8) * 512 + cc] = lp;
            } else {
                const float b0 = bias[cc], b1 = bias[cc + 1];
                Cf[(size_t)r * 512 + cc]           = v0 + b0;
                Cf[(size_t)r * 512 + cc + 1]       = v1 + b1;
                Cf[(size_t)(r + 8) * 512 + cc]     = v2 + b0;
                Cf[(size_t)(r + 8) * 512 + cc + 1] = v3 + b1;
            }
        }
}

// ----------------------------------------------------------------------------
// Flash attention with cp.async double-buffered K/V staging.
// ----------------------------------------------------------------------------
__global__ __launch_bounds__(256)
void flash_kernel(const __nv_bfloat16* __restrict__ Qh, const __nv_bfloat16* __restrict__ Ql,
                  const __nv_bfloat16* __restrict__ Kh, const __nv_bfloat16* __restrict__ Kl,
                  const __nv_bfloat16* __restrict__ Vh, const __nv_bfloat16* __restrict__ Vl,
                  __nv_bfloat16* __restrict__ Oh, __nv_bfloat16* __restrict__ Ol)
{
    extern __shared__ __nv_bfloat16 fsm[];

    const int z = blockIdx.y;
    const long long zo = z >> 3, zi = z & 7;
    const size_t gbase = (size_t)zo * 512 * 512 + (size_t)zi * 64;

    const int tid  = threadIdx.x;
    const int lane = tid & 31, warp = tid >> 5;
    const int g = lane >> 2, tg = lane & 3;
    const int lrow = lane & 7, lsel = lane >> 3;
    const int rowA = blockIdx.x * 128 + warp * 16 + g;

    // resident Q fragments
    unsigned qh[4][4], ql[4][4];
    #pragma unroll
    for (int kc = 0; kc < 4; kc++) {
        const int c = kc * 16 + tg * 2;
        qh[kc][0] = *(const unsigned*)&Qh[gbase + (size_t)rowA * 512 + c];
        qh[kc][1] = *(const unsigned*)&Qh[gbase + (size_t)(rowA + 8) * 512 + c];
        qh[kc][2] = *(const unsigned*)&Qh[gbase + (size_t)rowA * 512 + c + 8];
        qh[kc][3] = *(const unsigned*)&Qh[gbase + (size_t)(rowA + 8) * 512 + c + 8];
        ql[kc][0] = *(const unsigned*)&Ql[gbase + (size_t)rowA * 512 + c];
        ql[kc][1] = *(const unsigned*)&Ql[gbase + (size_t)(rowA + 8) * 512 + c];
        ql[kc][2] = *(const unsigned*)&Ql[gbase + (size_t)rowA * 512 + c + 8];
        ql[kc][3] = *(const unsigned*)&Ql[gbase + (size_t)(rowA + 8) * 512 + c + 8];
    }

    auto load_kv = [&](int kt, int s) {
        __nv_bfloat16* st = fsm + s * FSTG;
        #pragma unroll
        for (int j = 0; j < 2; j++) {
            const int idx = tid + j * 256;
            const int row = idx >> 3, q = (idx & 7) * 8;
            const size_t go = gbase + (size_t)(kt * 64 + row) * 512 + q;
            const unsigned so = row * 72 + q;
            cp16(smem_u32(st + so),            Kh + go);
            cp16(smem_u32(st + FARR + so),     Kl + go);
            cp16(smem_u32(st + 2 * FARR + so), Vh + go);
            cp16(smem_u32(st + 3 * FARR + so), Vl + go);
        }
    };

    float o[8][4];
    #pragma unroll
    for (int nd = 0; nd < 8; nd++)
        #pragma unroll
        for (int i = 0; i < 4; i++) o[nd][i] = 0.f;
    float m0 = -1e30f, m1 = -1e30f, l0 = 0.f, l1 = 0.f;

    load_kv(0, 0); cp_commit();
    load_kv(1, 1); cp_commit();

    for (int kt = 0; kt < 8; kt++) {
        const int s = kt & 1;
        if (kt < 7) cp_wait1(); else cp_wait0();
        __syncthreads();

        const __nv_bfloat16* sKh = fsm + s * FSTG;
        const __nv_bfloat16* sKl = sKh + FARR;
        const __nv_bfloat16* sVh = sKh + 2 * FARR;
        const __nv_bfloat16* sVl = sKh + 3 * FARR;

        // ---- S = Q K^T ----
        float sx[8][4];
        #pragma unroll
        for (int nt = 0; nt < 8; nt++)
            #pragma unroll
            for (int i = 0; i < 4; i++) sx[nt][i] = 0.f;

        #pragma unroll
        for (int kc = 0; kc < 4; kc++) {
            const int c0 = kc * 16;
            #pragma unroll
            for (int ntp = 0; ntp < 4; ntp++) {
                const int n0 = ntp * 16;
                unsigned bh4[4], bl4[4];
                const unsigned ea = smem_u32(sKh + (n0 + (lsel >> 1) * 8 + lrow) * 72 + c0 + (lsel & 1) * 8);
                const unsigned el = smem_u32(sKl + (n0 + (lsel >> 1) * 8 + lrow) * 72 + c0 + (lsel & 1) * 8);
                ldsm_x4(bh4, ea);
                ldsm_x4(bl4, el);
                mma16816(sx[2 * ntp],     qh[kc], bh4);
                mma16816(sx[2 * ntp],     qh[kc], bl4);
                mma16816(sx[2 * ntp],     ql[kc], bh4);
                mma16816(sx[2 * ntp + 1], qh[kc], bh4 + 2);
                mma16816(sx[2 * ntp + 1], qh[kc], bl4 + 2);
                mma16816(sx[2 * ntp + 1], ql[kc], bh4 + 2);
            }
        }

        // ---- online softmax ----
        float r0 = -1e30f, r1 = -1e30f;
        #pragma unroll
        for (int nt = 0; nt < 8; nt++) {
            r0 = fmaxf(r0, fmaxf(sx[nt][0], sx[nt][1]));
            r1 = fmaxf(r1, fmaxf(sx[nt][2], sx[nt][3]));
        }
        r0 = fmaxf(r0, __shfl_xor_sync(0xffffffffu, r0, 1));
        r0 = fmaxf(r0, __shfl_xor_sync(0xffffffffu, r0, 2));
        r1 = fmaxf(r1, __shfl_xor_sync(0xffffffffu, r1, 1));
        r1 = fmaxf(r1, __shfl_xor_sync(0xffffffffu, r1, 2));
        const float m0n = fmaxf(m0, r0), m1n = fmaxf(m1, r1);
        const float a0 = __expf(m0 - m0n), a1 = __expf(m1 - m1n);

        float ps0 = 0.f, ps1 = 0.f;
        #pragma unroll
        for (int nt = 0; nt < 8; nt++) {
            sx[nt][0] = __expf(sx[nt][0] - m0n);
            sx[nt][1] = __expf(sx[nt][1] - m0n);
            sx[nt][2] = __expf(sx[nt][2] - m1n);
            sx[nt][3] = __expf(sx[nt][3] - m1n);
            ps0 += sx[nt][0] + sx[nt][1];
            ps1 += sx[nt][2] + sx[nt][3];
        }
        m0 = m0n; m1 = m1n;
        l0 = l0 * a0 + ps0;
        l1 = l1 * a1 + ps1;
        #pragma unroll
        for (int nd = 0; nd < 8; nd++) {
            o[nd][0] *= a0; o[nd][1] *= a0;
            o[nd][2] *= a1; o[nd][3] *= a1;
        }

        // ---- O += P V ----
        #pragma unroll
        for (int kc = 0; kc < 4; kc++) {
            const int c0 = kc * 16;
            unsigned pah[4], pal[4];
            split_pack2(sx[2 * kc][0],     sx[2 * kc][1],     pah[0], pal[0]);
            split_pack2(sx[2 * kc][2],     sx[2 * kc][3],     pah[1], pal[1]);
            split_pack2(sx[2 * kc + 1][0], sx[2 * kc + 1][1], pah[2], pal[2]);
            split_pack2(sx[2 * kc + 1][2], sx[2 * kc + 1][3], pah[3], pal[3]);
            #pragma unroll
            for (int ndp = 0; ndp < 4; ndp++) {
                const int d0 = ndp * 16;
                unsigned vh4[4], vl4[4];
                const unsigned ea = smem_u32(sVh + (c0 + (lsel & 1) * 8 + lrow) * 72 + d0 + (lsel >> 1) * 8);
                const unsigned el = smem_u32(sVl + (c0 + (lsel & 1) * 8 + lrow) * 72 + d0 + (lsel >> 1) * 8);
                ldsm_x4_t(vh4, ea);
                ldsm_x4_t(vl4, el);
                mma16816(o[2 * ndp],     pah, vh4);
                mma16816(o[2 * ndp],     pah, vl4);
                mma16816(o[2 * ndp],     pal, vh4);
                mma16816(o[2 * ndp + 1], pah, vh4 + 2);
                mma16816(o[2 * ndp + 1], pah, vl4 + 2);
                mma16816(o[2 * ndp + 1], pal, vh4 + 2);
            }
        }
        __syncthreads();
        if (kt + 2 < 8) { load_kv(kt + 2, s); cp_commit(); }
    }

    l0 += __shfl_xor_sync(0xffffffffu, l0, 1);
    l0 += __shfl_xor_sync(0xffffffffu, l0, 2);
    l1 += __shfl_xor_sync(0xffffffffu, l1, 1);
    l1 += __shfl_xor_sync(0xffffffffu, l1, 2);
    const float inv0 = 1.f / l0, inv1 = 1.f / l1;

    #pragma unroll
    for (int nd = 0; nd < 8; nd++) {
        const int cc = nd * 8 + tg * 2;
        unsigned hp, lp;
        split_pack2(o[nd][0] * inv0, o[nd][1] * inv0, hp, lp);
        *(unsigned*)&Oh[gbase + (size_t)rowA * 512 + cc] = hp;
        *(unsigned*)&Ol[gbase + (size_t)rowA * 512 + cc] = lp;
        split_pack2(o[nd][2] * inv1, o[nd][3] * inv1, hp, lp);
        *(unsigned*)&Oh[gbase + (size_t)(rowA + 8) * 512 + cc] = hp;
        *(unsigned*)&Ol[gbase + (size_t)(rowA + 8) * 512 + cc] = lp;
    }
}

extern "C" void kernel_launch(void* const* d_in, const int* in_sizes, int n_in,
                              void* d_out, int out_size)
{
    const float* q_in  = (const float*)d_in[0];
    const float* kv_in = (const float*)d_in[1];
    const float* Wq    = (const float*)d_in[2];
    const float* Wk    = (const float*)d_in[3];
    const float* Wv    = (const float*)d_in[4];
    const float* Wo    = (const float*)d_in[5];
    const float* bo    = (const float*)d_in[6];
    float* out = (float*)d_out;

    __nv_bfloat16 *qh, *ql, *kvh, *kvl, *wh, *wl;
    __nv_bfloat16 *Qh, *Ql, *Kh, *Kl, *Vh, *Vl, *Oh, *Ol;
    cudaGetSymbolAddress((void**)&qh,  g_qh);  cudaGetSymbolAddress((void**)&ql,  g_ql);
    cudaGetSymbolAddress((void**)&kvh, g_kvh); cudaGetSymbolAddress((void**)&kvl, g_kvl);
    cudaGetSymbolAddress((void**)&wh,  g_wh);  cudaGetSymbolAddress((void**)&wl,  g_wl);
    cudaGetSymbolAddress((void**)&Qh,  g_Qh);  cudaGetSymbolAddress((void**)&Ql,  g_Ql);
    cudaGetSymbolAddress((void**)&Kh,  g_Kh);  cudaGetSymbolAddress((void**)&Kl,  g_Kl);
    cudaGetSymbolAddress((void**)&Vh,  g_Vh);  cudaGetSymbolAddress((void**)&Vl,  g_Vl);
    cudaGetSymbolAddress((void**)&Oh,  g_Oh);  cudaGetSymbolAddress((void**)&Ol,  g_Ol);

    cudaFuncSetAttribute(gemm_bf16_kernel<1>, cudaFuncAttributeMaxDynamicSharedMemorySize, SMEM_DENSE);
    cudaFuncSetAttribute(gemm_bf16_kernel<0>, cudaFuncAttributeMaxDynamicSharedMemorySize, SMEM_DENSE);
    cudaFuncSetAttribute(flash_kernel,        cudaFuncAttributeMaxDynamicSharedMemorySize, SMEM_FLASH);

    const dim3 ggrid(512 / 128, NTOK / 128, 1);

    // 1-3: splits
    split_kernel<<<(NELEM / 4 + 255) / 256, 256>>>(q_in,  qh,  ql,  NELEM / 4);
    split_kernel<<<(NELEM / 4 + 255) / 256, 256>>>(kv_in, kvh, kvl, NELEM / 4);
    split4_kernel<<<dim3(WELEM / 4 / 256, 1, 4), 256>>>(Wq, Wk, Wv, Wo, wh, wl);

    // 4-6: projections (launches 5 and 6 are dense GEMMs for the ncu slot)
    gemm_bf16_kernel<1><<<ggrid, 256, SMEM_DENSE>>>(qh,  ql,  wh,             wl,             nullptr, Qh, Ql, nullptr, 0.125f);
    gemm_bf16_kernel<1><<<ggrid, 256, SMEM_DENSE>>>(kvh, kvl, wh + WELEM,     wl + WELEM,     nullptr, Kh, Kl, nullptr, 1.f);
    gemm_bf16_kernel<1><<<ggrid, 256, SMEM_DENSE>>>(kvh, kvl, wh + 2 * WELEM, wl + 2 * WELEM, nullptr, Vh, Vl, nullptr, 1.f);

    // 7: fused flash attention (cp.async pipelined)
    flash_kernel<<<dim3(4, 256), 256, SMEM_FLASH>>>(Qh, Ql, Kh, Kl, Vh, Vl, Oh, Ol);

    // 8: output projection + bias
    gemm_bf16_kernel<0><<<ggrid, 256, SMEM_DENSE>>>(Oh, Ol, wh + 3 * WELEM, wl + 3 * WELEM, out, nullptr, nullptr, bo, 1.f);
}